// round 13
// baseline (speedup 1.0000x reference)
#include <cuda_runtime.h>
#include <cuda_fp16.h>
#include <math.h>
#include <stdint.h>

#define N_B 2
#define L_S 2048
#define EMB 1024
#define NH  16
#define HD  64
#define PITCH 72

// log2(e) / sqrt(EMB) — folded into the Q projection output
#define CEXP 0.045084220027780106f

__device__ __align__(128) __half g_qp[N_B * NH * L_S * HD]; // [n,h,l,d] (pre-scaled by CEXP)
__device__ __align__(128) __half g_kp[N_B * NH * L_S * HD];
__device__ __align__(128) __half g_vp[N_B * NH * L_S * HD];
__device__ __align__(128) __half g_att[N_B * L_S * EMB];    // [n,l,e]
__device__ __align__(128) __half g_woh[EMB * EMB];
__device__ __align__(128) uint32_t g_mpack[N_B * L_S * 64]; // packed mask bits
__device__ unsigned char g_mflag[N_B * 32 * 32];            // all-ones flag per 64x64 tile

// ---------------------------------------------------------------------------
__device__ __forceinline__ uint32_t h2exp2(uint32_t x) {
    uint32_t r;
    asm("ex2.approx.f16x2 %0, %1;\n" : "=r"(r) : "r"(x));
    return r;
}

__device__ __forceinline__ void mma16816(float c[4],
    uint32_t a0, uint32_t a1, uint32_t a2, uint32_t a3,
    uint32_t b0, uint32_t b1)
{
    asm volatile(
        "mma.sync.aligned.m16n8k16.row.col.f32.f16.f16.f32 "
        "{%0,%1,%2,%3}, {%4,%5,%6,%7}, {%8,%9}, {%0,%1,%2,%3};\n"
        : "+f"(c[0]), "+f"(c[1]), "+f"(c[2]), "+f"(c[3])
        : "r"(a0), "r"(a1), "r"(a2), "r"(a3), "r"(b0), "r"(b1));
}

__device__ __forceinline__ uint32_t packh2(float a, float b) {
    union { __half2 h2; uint32_t u; } cvt;
    cvt.h2 = __floats2half2_rn(a, b);
    return cvt.u;
}

__device__ __forceinline__ void ldsm_x4(uint32_t& r0, uint32_t& r1,
                                        uint32_t& r2, uint32_t& r3, const __half* p)
{
    uint32_t a = (uint32_t)__cvta_generic_to_shared(p);
    asm volatile("ldmatrix.sync.aligned.m8n8.x4.shared.b16 {%0,%1,%2,%3}, [%4];\n"
                 : "=r"(r0), "=r"(r1), "=r"(r2), "=r"(r3) : "r"(a));
}

__device__ __forceinline__ void ldsm_x4_t(uint32_t& r0, uint32_t& r1,
                                          uint32_t& r2, uint32_t& r3, const __half* p)
{
    uint32_t a = (uint32_t)__cvta_generic_to_shared(p);
    asm volatile("ldmatrix.sync.aligned.m8n8.x4.trans.shared.b16 {%0,%1,%2,%3}, [%4];\n"
                 : "=r"(r0), "=r"(r1), "=r"(r2), "=r"(r3) : "r"(a));
}

__device__ __forceinline__ void cp16(__half* s, const __half* g) {
    uint32_t a = (uint32_t)__cvta_generic_to_shared(s);
    asm volatile("cp.async.cg.shared.global [%0], [%1], 16;\n" :: "r"(a), "l"(g));
}
__device__ __forceinline__ void cp_commit() {
    asm volatile("cp.async.commit_group;\n");
}
template<int N> __device__ __forceinline__ void cp_wait() {
    asm volatile("cp.async.wait_group %0;\n" :: "n"(N));
}

// ---------------------------------------------------------------------------
// Fused mask preprocessing: pack bits + per-64x64-tile all-ones flags.
// ---------------------------------------------------------------------------
__global__ __launch_bounds__(256) void mask_prep(const int* __restrict__ mask)
{
    __shared__ int flags_s[32];
    const int b = blockIdx.x;
    const int n = b >> 5, qt = b & 31;
    const int tid = threadIdx.x;

    if (tid < 32) flags_s[tid] = 1;
    __syncthreads();

    const int r  = tid >> 2;
    const int w0 = (tid & 3) * 16;
    const int row = qt * 64 + r;
    const int* src = mask + ((size_t)n * L_S + row) * L_S + (size_t)w0 * 32;
    uint32_t* dst = &g_mpack[((size_t)n * L_S + row) * 64 + w0];

    int notall = 0;
    #pragma unroll
    for (int j = 0; j < 16; j++) {
        const int* p = src + j * 32;
        uint32_t bits = 0;
        #pragma unroll
        for (int i = 0; i < 8; i++) {
            int4 v = *(const int4*)(p + i * 4);
            bits |= (v.x != 0 ? 1u : 0u) << (i * 4);
            bits |= (v.y != 0 ? 1u : 0u) << (i * 4 + 1);
            bits |= (v.z != 0 ? 1u : 0u) << (i * 4 + 2);
            bits |= (v.w != 0 ? 1u : 0u) << (i * 4 + 3);
        }
        dst[j] = bits;
        if (bits != 0xFFFFFFFFu) notall |= 1 << (j >> 1);
    }
    #pragma unroll
    for (int j = 0; j < 8; j++)
        if (notall & (1 << j)) atomicAnd(&flags_s[(w0 >> 1) + j], 0);
    __syncthreads();

    if (tid < 32)
        g_mflag[((size_t)n * 32 + qt) * 32 + tid] = (unsigned char)flags_s[tid];
}

// ---------------------------------------------------------------------------
// Kernel 1: projections via fp16 mma. blockIdx.y: 0=q,1=k,2=v.
// ---------------------------------------------------------------------------
__global__ __launch_bounds__(256) void proj_mma(
    const float* __restrict__ q_in, const float* __restrict__ k_in,
    const float* __restrict__ v_in,
    const float* __restrict__ Wq, const float* __restrict__ Wk,
    const float* __restrict__ Wv)
{
    const float* x; const float* W; __half* out;
    if (blockIdx.y == 0)      { x = q_in; W = Wq; out = g_qp; }
    else if (blockIdx.y == 1) { x = k_in; W = Wk; out = g_kp; }
    else                      { x = v_in; W = Wv; out = g_vp; }
    const float oscale = (blockIdx.y == 0) ? CEXP : 1.0f;

    __shared__ __half Xs[128 * PITCH];
    __shared__ __half Ws[64 * PITCH];

    const int row0 = blockIdx.x * 128;
    const int tid  = threadIdx.x;

    #pragma unroll
    for (int it = 0; it < 4; it++) {
        int idx = tid * 4 + it * 1024;
        int r = idx >> 6, c = idx & 63;
        float4 w4 = *(const float4*)(W + idx);
        *(__half2*)&Ws[r * PITCH + c]     = __floats2half2_rn(w4.x, w4.y);
        *(__half2*)&Ws[r * PITCH + c + 2] = __floats2half2_rn(w4.z, w4.w);
    }
    #pragma unroll
    for (int it = 0; it < 8; it++) {
        int idx = tid * 4 + it * 1024;
        int r = idx >> 6, c = idx & 63;
        int grow = row0 + r;
        int n = grow >> 15, rem = grow & 32767;
        int l = rem >> 4, h = rem & 15;
        float4 v4 = *(const float4*)(x + ((size_t)(n * L_S + l) * EMB + h * HD + c));
        *(__half2*)&Xs[r * PITCH + c]     = __floats2half2_rn(v4.x, v4.y);
        *(__half2*)&Xs[r * PITCH + c + 2] = __floats2half2_rn(v4.z, v4.w);
    }
    __syncthreads();

    const int warp = tid >> 5, lane = tid & 31;
    const int g = lane >> 2, t4 = lane & 3;
    const int mw = warp * 16;
    const int lr = lane & 7, lc = lane >> 3;

    uint32_t a[4][4];
    #pragma unroll
    for (int kc = 0; kc < 4; kc++) {
        a[kc][0] = *(const uint32_t*)&Xs[(mw + g    ) * PITCH + kc * 16 + 2 * t4];
        a[kc][1] = *(const uint32_t*)&Xs[(mw + g + 8) * PITCH + kc * 16 + 2 * t4];
        a[kc][2] = *(const uint32_t*)&Xs[(mw + g    ) * PITCH + kc * 16 + 2 * t4 + 8];
        a[kc][3] = *(const uint32_t*)&Xs[(mw + g + 8) * PITCH + kc * 16 + 2 * t4 + 8];
    }

    float o[8][4];
    #pragma unroll
    for (int nt = 0; nt < 8; nt++) { o[nt][0]=o[nt][1]=o[nt][2]=o[nt][3]=0.f; }

    #pragma unroll
    for (int nt = 0; nt < 8; nt++) {
        #pragma unroll
        for (int kc0 = 0; kc0 < 4; kc0 += 2) {
            uint32_t b0, b1, b2, b3;
            ldsm_x4(b0, b1, b2, b3,
                &Ws[(nt * 8 + lr) * PITCH + kc0 * 16 + lc * 8]);
            mma16816(o[nt], a[kc0][0], a[kc0][1], a[kc0][2], a[kc0][3], b0, b1);
            mma16816(o[nt], a[kc0+1][0], a[kc0+1][1], a[kc0+1][2], a[kc0+1][3], b2, b3);
        }
    }

    #pragma unroll
    for (int nt = 0; nt < 8; nt++) {
        int e = nt * 8 + 2 * t4;
        int grow = row0 + mw + g;
        int n = grow >> 15, rem = grow & 32767;
        int l = rem >> 4, h = rem & 15;
        *(__half2*)(out + ((size_t)(n * NH + h) * L_S + l) * HD + e)
            = __floats2half2_rn(o[nt][0] * oscale, o[nt][1] * oscale);
        grow += 8; n = grow >> 15; rem = grow & 32767; l = rem >> 4; h = rem & 15;
        *(__half2*)(out + ((size_t)(n * NH + h) * L_S + l) * HD + e)
            = __floats2half2_rn(o[nt][2] * oscale, o[nt][3] * oscale);
    }
}

// ---------------------------------------------------------------------------
__global__ __launch_bounds__(256) void wo_cvt(const float* __restrict__ w)
{
    int i = (blockIdx.x * 256 + threadIdx.x) * 4;
    float4 v = *(const float4*)(w + i);
    *(__half2*)(g_woh + i)     = __floats2half2_rn(v.x, v.y);
    *(__half2*)(g_woh + i + 2) = __floats2half2_rn(v.z, v.w);
}

// ---------------------------------------------------------------------------
// Kernel 2: flash attention, 32 q-rows per warp (two m16 row-groups sharing
// every K/V B-fragment ldsm -> smem read volume halved). BM=128, 4 warps.
// Single-pass softmax via ex2.approx.f16x2; row sums via ones-column (ne=8).
// 3-slot cp.async ring, prefetch distance 2. grid (32, 16), (128,3).
// ---------------------------------------------------------------------------
__global__ __launch_bounds__(128, 3) void attn12()
{
    extern __shared__ __half sm8[];
    __half* Ks = sm8;                       // 3 slots of 64*PITCH
    __half* Vs = sm8 + 3 * 64 * PITCH;      // 3 slots of 64*PITCH

    const int nh = blockIdx.x;
    const int qt = blockIdx.y;              // 128-row tile (0..15)
    const int n  = nh >> 4, h = nh & 15;
    const int q0 = qt * 128;

    const __half* Qg = g_qp + (size_t)nh * L_S * HD;
    const __half* Kg = g_kp + (size_t)nh * L_S * HD;
    const __half* Vg = g_vp + (size_t)nh * L_S * HD;

    const int tid = threadIdx.x;
    const int warp = tid >> 5, lane = tid & 31;
    const int g = lane >> 2, t4 = lane & 3;
    const int mw = warp * 32;               // 32 rows per warp
    const int lr = lane & 7, lc = lane >> 3;

    // Q A-fragments for both row groups, from gmem (one-time)
    uint32_t qa0[4][4], qa1[4][4];
    {
        const __half* Qr0 = Qg + (size_t)(q0 + mw + g     ) * HD;
        const __half* Qr1 = Qg + (size_t)(q0 + mw + g +  8) * HD;
        const __half* Qr2 = Qg + (size_t)(q0 + mw + g + 16) * HD;
        const __half* Qr3 = Qg + (size_t)(q0 + mw + g + 24) * HD;
        #pragma unroll
        for (int kc = 0; kc < 4; kc++) {
            qa0[kc][0] = *(const uint32_t*)&Qr0[kc * 16 + 2 * t4];
            qa0[kc][1] = *(const uint32_t*)&Qr1[kc * 16 + 2 * t4];
            qa0[kc][2] = *(const uint32_t*)&Qr0[kc * 16 + 2 * t4 + 8];
            qa0[kc][3] = *(const uint32_t*)&Qr1[kc * 16 + 2 * t4 + 8];
            qa1[kc][0] = *(const uint32_t*)&Qr2[kc * 16 + 2 * t4];
            qa1[kc][1] = *(const uint32_t*)&Qr3[kc * 16 + 2 * t4];
            qa1[kc][2] = *(const uint32_t*)&Qr2[kc * 16 + 2 * t4 + 8];
            qa1[kc][3] = *(const uint32_t*)&Qr3[kc * 16 + 2 * t4 + 8];
        }
    }

    // per-warp mask flag row: warp's 32 rows lie in one 64-row band
    const unsigned char* flags =
        g_mflag + ((size_t)n * 32 + ((q0 + mw) >> 6)) * 32;
    const uint32_t* Mp = g_mpack + (size_t)n * L_S * 64;

    auto load_kv = [&](int t) {
        __half* dk = Ks + (t % 3) * 64 * PITCH;
        __half* dv = Vs + (t % 3) * 64 * PITCH;
        const __half* sk = Kg + (size_t)t * 64 * HD;
        const __half* sv = Vg + (size_t)t * 64 * HD;
        #pragma unroll
        for (int it = 0; it < 4; it++) {
            int c = tid + it * 128;
            int r = c >> 3, off = (c & 7) * 8;
            cp16(&dk[r * PITCH + off], &sk[(size_t)r * HD + off]);
        }
        #pragma unroll
        for (int it = 0; it < 4; it++) {
            int c = tid + it * 128;
            int r = c >> 3, off = (c & 7) * 8;
            cp16(&dv[r * PITCH + off], &sv[(size_t)r * HD + off]);
        }
        cp_commit();
    };

    uint32_t pa0[4][4], pa1[4][4];

    // GEMM1 + softmax for both row groups; K B-fragments loaded ONCE.
    auto gemm1 = [&](const __half* Kt, int t) {
        const bool do_mask = !flags[t];
        uint64_t w0 = 0, w1 = 0, w2 = 0, w3 = 0;
        if (do_mask) {
            w0 = *(const uint64_t*)&Mp[(size_t)(q0 + mw + g     ) * 64 + t * 2];
            w1 = *(const uint64_t*)&Mp[(size_t)(q0 + mw + g +  8) * 64 + t * 2];
            w2 = *(const uint64_t*)&Mp[(size_t)(q0 + mw + g + 16) * 64 + t * 2];
            w3 = *(const uint64_t*)&Mp[(size_t)(q0 + mw + g + 24) * 64 + t * 2];
        }
        #pragma unroll
        for (int ntp = 0; ntp < 4; ntp++) {
            const int nt0 = 2 * ntp, nt1 = 2 * ntp + 1;
            float s00[4] = {0.f,0.f,0.f,0.f};   // rg0, nt0
            float s01[4] = {0.f,0.f,0.f,0.f};   // rg0, nt1
            float s10[4] = {0.f,0.f,0.f,0.f};   // rg1, nt0
            float s11[4] = {0.f,0.f,0.f,0.f};   // rg1, nt1
            #pragma unroll
            for (int kc0 = 0; kc0 < 4; kc0 += 2) {
                uint32_t b0, b1, b2, b3;
                ldsm_x4(b0, b1, b2, b3,
                    &Kt[(nt0 * 8 + lr) * PITCH + kc0 * 16 + lc * 8]);
                mma16816(s00, qa0[kc0][0], qa0[kc0][1], qa0[kc0][2], qa0[kc0][3], b0, b1);
                mma16816(s00, qa0[kc0+1][0], qa0[kc0+1][1], qa0[kc0+1][2], qa0[kc0+1][3], b2, b3);
                mma16816(s10, qa1[kc0][0], qa1[kc0][1], qa1[kc0][2], qa1[kc0][3], b0, b1);
                mma16816(s10, qa1[kc0+1][0], qa1[kc0+1][1], qa1[kc0+1][2], qa1[kc0+1][3], b2, b3);
                ldsm_x4(b0, b1, b2, b3,
                    &Kt[(nt1 * 8 + lr) * PITCH + kc0 * 16 + lc * 8]);
                mma16816(s01, qa0[kc0][0], qa0[kc0][1], qa0[kc0][2], qa0[kc0][3], b0, b1);
                mma16816(s01, qa0[kc0+1][0], qa0[kc0+1][1], qa0[kc0+1][2], qa0[kc0+1][3], b2, b3);
                mma16816(s11, qa1[kc0][0], qa1[kc0][1], qa1[kc0][2], qa1[kc0][3], b0, b1);
                mma16816(s11, qa1[kc0+1][0], qa1[kc0+1][1], qa1[kc0+1][2], qa1[kc0+1][3], b2, b3);
            }
            if (do_mask) {
                int bit0 = nt0 * 8 + 2 * t4;
                int bit1 = nt1 * 8 + 2 * t4;
                if (!((w0 >> bit0) & 1))       s00[0] = -1e30f;
                if (!((w0 >> (bit0 + 1)) & 1)) s00[1] = -1e30f;
                if (!((w1 >> bit0) & 1))       s00[2] = -1e30f;
                if (!((w1 >> (bit0 + 1)) & 1)) s00[3] = -1e30f;
                if (!((w0 >> bit1) & 1))       s01[0] = -1e30f;
                if (!((w0 >> (bit1 + 1)) & 1)) s01[1] = -1e30f;
                if (!((w1 >> bit1) & 1))       s01[2] = -1e30f;
                if (!((w1 >> (bit1 + 1)) & 1)) s01[3] = -1e30f;
                if (!((w2 >> bit0) & 1))       s10[0] = -1e30f;
                if (!((w2 >> (bit0 + 1)) & 1)) s10[1] = -1e30f;
                if (!((w3 >> bit0) & 1))       s10[2] = -1e30f;
                if (!((w3 >> (bit0 + 1)) & 1)) s10[3] = -1e30f;
                if (!((w2 >> bit1) & 1))       s11[0] = -1e30f;
                if (!((w2 >> (bit1 + 1)) & 1)) s11[1] = -1e30f;
                if (!((w3 >> bit1) & 1))       s11[2] = -1e30f;
                if (!((w3 >> (bit1 + 1)) & 1)) s11[3] = -1e30f;
            }
            pa0[ntp][0] = h2exp2(packh2(s00[0], s00[1]));
            pa0[ntp][1] = h2exp2(packh2(s00[2], s00[3]));
            pa0[ntp][2] = h2exp2(packh2(s01[0], s01[1]));
            pa0[ntp][3] = h2exp2(packh2(s01[2], s01[3]));
            pa1[ntp][0] = h2exp2(packh2(s10[0], s10[1]));
            pa1[ntp][1] = h2exp2(packh2(s10[2], s10[3]));
            pa1[ntp][2] = h2exp2(packh2(s11[0], s11[1]));
            pa1[ntp][3] = h2exp2(packh2(s11[2], s11[3]));
        }
    };

    // Accumulators: o0/o1 for the two row groups; [8] = ones-column (row sums)
    float o0[9][4], o1[9][4];
    #pragma unroll
    for (int ne = 0; ne < 9; ne++) {
        o0[ne][0]=o0[ne][1]=o0[ne][2]=o0[ne][3]=0.f;
        o1[ne][0]=o1[ne][1]=o1[ne][2]=o1[ne][3]=0.f;
    }

    // GEMM2: V B-fragments loaded ONCE, fed to both row groups.
    auto gemm2 = [&](int kt) {
        const __half* Vt = Vs + (kt % 3) * 64 * PITCH;
        #pragma unroll
        for (int ne = 0; ne < 9; ne++) {
            #pragma unroll
            for (int kc0 = 0; kc0 < 4; kc0 += 2) {
                uint32_t b0, b1, b2, b3;
                ldsm_x4_t(b0, b1, b2, b3,
                    &Vt[(kc0 * 16 + lane) * PITCH + ne * 8]);
                mma16816(o0[ne], pa0[kc0][0], pa0[kc0][1], pa0[kc0][2], pa0[kc0][3], b0, b1);
                mma16816(o0[ne], pa0[kc0+1][0], pa0[kc0+1][1], pa0[kc0+1][2], pa0[kc0+1][3], b2, b3);
                mma16816(o1[ne], pa1[kc0][0], pa1[kc0][1], pa1[kc0][2], pa1[kc0][3], b0, b1);
                mma16816(o1[ne], pa1[kc0+1][0], pa1[kc0+1][1], pa1[kc0+1][2], pa1[kc0+1][3], b2, b3);
            }
        }
    };

    // Prologue: load tiles 0 and 1; init V padding (ones col 64, zeros 65-71)
    load_kv(0);
    load_kv(1);
    {
        __half pad[8];
        pad[0] = __float2half(1.0f);
        #pragma unroll
        for (int i = 1; i < 8; i++) pad[i] = __float2half(0.0f);
        for (int r = tid; r < 3 * 64; r += 128)
            *(uint4*)&Vs[r * PITCH + 64] = *(const uint4*)pad;
    }

    const int NT = L_S / 64;
    #pragma unroll 1
    for (int kt = 0; kt < NT; kt++) {
        cp_wait<1>();           // tile kt resident (only kt+1's group may pend)
        __syncthreads();        // all warps past reads of slot (kt+2)%3

        if (kt + 2 < NT) load_kv(kt + 2);   // slot (kt+2)%3: free since kt-1
        else cp_commit();                    // keep group count uniform

        gemm1(Ks + (kt % 3) * 64 * PITCH, kt);
        gemm2(kt);
    }

    // row sums from ones-column; broadcast from t4==0 lane of each quad
    float l0 = __shfl_sync(0xffffffffu, o0[8][0], lane & ~3);
    float l1 = __shfl_sync(0xffffffffu, o0[8][2], lane & ~3);
    float l2 = __shfl_sync(0xffffffffu, o1[8][0], lane & ~3);
    float l3 = __shfl_sync(0xffffffffu, o1[8][2], lane & ~3);

    float inv0 = 1.f / l0, inv1 = 1.f / l1, inv2 = 1.f / l2, inv3 = 1.f / l3;
    int row = q0 + mw + g;
    __half* base0 = g_att + ((size_t)n * L_S + row) * EMB + h * HD;
    __half* base1 = base0 + (size_t) 8 * EMB;
    __half* base2 = base0 + (size_t)16 * EMB;
    __half* base3 = base0 + (size_t)24 * EMB;
    #pragma unroll
    for (int ne = 0; ne < 8; ne++) {
        int e = ne * 8 + 2 * t4;
        *(__half2*)(base0 + e) = __floats2half2_rn(o0[ne][0] * inv0, o0[ne][1] * inv0);
        *(__half2*)(base1 + e) = __floats2half2_rn(o0[ne][2] * inv1, o0[ne][3] * inv1);
        *(__half2*)(base2 + e) = __floats2half2_rn(o1[ne][0] * inv2, o1[ne][1] * inv2);
        *(__half2*)(base3 + e) = __floats2half2_rn(o1[ne][2] * inv3, o1[ne][3] * inv3);
    }
}

// ---------------------------------------------------------------------------
// Kernel 3: out projection, BM=128 x BN=128 per block, cp.async 2-stage.
// ---------------------------------------------------------------------------
__global__ __launch_bounds__(256) void out_mma3(
    const float* __restrict__ bo, float* __restrict__ out)
{
    extern __shared__ __half sm[];
    __half* As[2] = { sm, sm + 128 * PITCH };
    __half* Bs[2] = { sm + 2 * 128 * PITCH, sm + 3 * 128 * PITCH };

    const int m0 = blockIdx.x * 128;
    const int e0 = blockIdx.y * 128;
    const int tid = threadIdx.x;
    const int warp = tid >> 5, lane = tid & 31;
    const int g = lane >> 2, t4 = lane & 3;
    const int mw = warp * 16;
    const int lr = lane & 7, lc = lane >> 3;

    auto load_ab = [&](int f, int b) {
        const int f0 = f * 64;
        #pragma unroll
        for (int it = 0; it < 4; it++) {
            int c = tid + it * 256;
            int r = c >> 3, off = (c & 7) * 8;
            cp16(&As[b][r * PITCH + off], &g_att[(size_t)(m0 + r) * EMB + f0 + off]);
        }
        #pragma unroll
        for (int it = 0; it < 4; it++) {
            int c = tid + it * 256;
            int r = c >> 3, off = (c & 7) * 8;
            cp16(&Bs[b][r * PITCH + off], &g_woh[(size_t)(e0 + r) * EMB + f0 + off]);
        }
        cp_commit();
    };

    float o[16][4];
    #pragma unroll
    for (int nt = 0; nt < 16; nt++) { o[nt][0]=o[nt][1]=o[nt][2]=o[nt][3]=0.f; }

    load_ab(0, 0);
    load_ab(1, 1);

    const int NF = EMB / 64;
    for (int f = 0; f < NF; f++) {
        const int b = f & 1;
        if (f == NF - 1) cp_wait<0>(); else cp_wait<1>();
        __syncthreads();

        uint32_t a[4][4];
        #pragma unroll
        for (int kc = 0; kc < 4; kc++) {
            ldsm_x4(a[kc][0], a[kc][1], a[kc][2], a[kc][3],
                &As[b][(mw + lr + ((lane >> 3) & 1) * 8) * PITCH
                       + kc * 16 + (lane >> 4) * 8]);
        }
        #pragma unroll
        for (int nt = 0; nt < 16; nt++) {
            #pragma unroll
            for (int kc0 = 0; kc0 < 4; kc0 += 2) {
                uint32_t b0, b1, b2, b3;
                ldsm_x4(b0, b1, b2, b3,
                    &Bs[b][(nt * 8 + lr) * PITCH + kc0 * 16 + lc * 8]);
                mma16816(o[nt], a[kc0][0], a[kc0][1], a[kc0][2], a[kc0][3], b0, b1);
                mma16816(o[nt], a[kc0+1][0], a[kc0+1][1], a[kc0+1][2], a[kc0+1][3], b2, b3);
            }
        }

        __syncthreads();
        if (f + 2 < NF) load_ab(f + 2, b);
    }

    #pragma unroll
    for (int nt = 0; nt < 16; nt++) {
        int e = e0 + nt * 8 + 2 * t4;
        float b0v = bo[e], b1v = bo[e + 1];
        float2* d0 = (float2*)(out + (size_t)(m0 + mw + g    ) * EMB + e);
        float2* d1 = (float2*)(out + (size_t)(m0 + mw + g + 8) * EMB + e);
        *d0 = make_float2(o[nt][0] + b0v, o[nt][1] + b1v);
        *d1 = make_float2(o[nt][2] + b0v, o[nt][3] + b1v);
    }
}

// ---------------------------------------------------------------------------
extern "C" void kernel_launch(void* const* d_in, const int* in_sizes, int n_in,
                              void* d_out, int out_size)
{
    const float* values  = (const float*)d_in[0];
    const float* keys    = (const float*)d_in[1];
    const float* queries = (const float*)d_in[2];
    const int*   mask    = (const int*)  d_in[3];
    const float* Wv      = (const float*)d_in[4];
    const float* Wk      = (const float*)d_in[5];
    const float* Wq      = (const float*)d_in[6];
    const float* Wo      = (const float*)d_in[7];
    const float* bo      = (const float*)d_in[8];
    float* out = (float*)d_out;

    proj_mma<<<dim3(512, 3), 256>>>(queries, keys, values, Wq, Wk, Wv);
    wo_cvt<<<1024, 256>>>(Wo);
    mask_prep<<<N_B * 32, 256>>>(mask);

    const int smem_attn = 6 * 64 * PITCH * sizeof(__half);   // 55296 B
    cudaFuncSetAttribute(attn12, cudaFuncAttributeMaxDynamicSharedMemorySize, smem_attn);
    attn12<<<dim3(N_B * NH, L_S / 128), 128, smem_attn>>>();

    const int smem_out = 4 * 128 * PITCH * sizeof(__half);   // 73728 B
    cudaFuncSetAttribute(out_mma3, cudaFuncAttributeMaxDynamicSharedMemorySize, smem_out);
    out_mma3<<<dim3((N_B * L_S) / 128, EMB / 128), 256, smem_out>>>(bo, out);
}

// round 14
// speedup vs baseline: 1.1263x; 1.1263x over previous
#include <cuda_runtime.h>
#include <cuda_fp16.h>
#include <math.h>
#include <stdint.h>

#define N_B 2
#define L_S 2048
#define EMB 1024
#define NH  16
#define HD  64
#define PITCH 72

// log2(e) / sqrt(EMB) — folded into the Q projection output
#define CEXP 0.045084220027780106f

__device__ __align__(128) __half g_qp[N_B * NH * L_S * HD]; // [n,h,l,d] (pre-scaled by CEXP)
__device__ __align__(128) __half g_kp[N_B * NH * L_S * HD];
__device__ __align__(128) __half g_vp[N_B * NH * L_S * HD];
__device__ __align__(128) __half g_att[N_B * L_S * EMB];    // [n,l,e]
__device__ __align__(128) __half g_woh[EMB * EMB];
__device__ __align__(128) uint32_t g_mpack[N_B * L_S * 64]; // packed mask bits
__device__ unsigned char g_mflag[N_B * 32 * 32];            // all-ones flag per 64x64 tile

// ---------------------------------------------------------------------------
__device__ __forceinline__ uint32_t h2exp2(uint32_t x) {
    uint32_t r;
    asm("ex2.approx.f16x2 %0, %1;\n" : "=r"(r) : "r"(x));
    return r;
}

__device__ __forceinline__ void mma16816(float c[4],
    uint32_t a0, uint32_t a1, uint32_t a2, uint32_t a3,
    uint32_t b0, uint32_t b1)
{
    asm volatile(
        "mma.sync.aligned.m16n8k16.row.col.f32.f16.f16.f32 "
        "{%0,%1,%2,%3}, {%4,%5,%6,%7}, {%8,%9}, {%0,%1,%2,%3};\n"
        : "+f"(c[0]), "+f"(c[1]), "+f"(c[2]), "+f"(c[3])
        : "r"(a0), "r"(a1), "r"(a2), "r"(a3), "r"(b0), "r"(b1));
}

__device__ __forceinline__ uint32_t packh2(float a, float b) {
    union { __half2 h2; uint32_t u; } cvt;
    cvt.h2 = __floats2half2_rn(a, b);
    return cvt.u;
}

__device__ __forceinline__ void ldsm_x4(uint32_t& r0, uint32_t& r1,
                                        uint32_t& r2, uint32_t& r3, const __half* p)
{
    uint32_t a = (uint32_t)__cvta_generic_to_shared(p);
    asm volatile("ldmatrix.sync.aligned.m8n8.x4.shared.b16 {%0,%1,%2,%3}, [%4];\n"
                 : "=r"(r0), "=r"(r1), "=r"(r2), "=r"(r3) : "r"(a));
}

__device__ __forceinline__ void ldsm_x4_t(uint32_t& r0, uint32_t& r1,
                                          uint32_t& r2, uint32_t& r3, const __half* p)
{
    uint32_t a = (uint32_t)__cvta_generic_to_shared(p);
    asm volatile("ldmatrix.sync.aligned.m8n8.x4.trans.shared.b16 {%0,%1,%2,%3}, [%4];\n"
                 : "=r"(r0), "=r"(r1), "=r"(r2), "=r"(r3) : "r"(a));
}

__device__ __forceinline__ void cp16(__half* s, const __half* g) {
    uint32_t a = (uint32_t)__cvta_generic_to_shared(s);
    asm volatile("cp.async.cg.shared.global [%0], [%1], 16;\n" :: "r"(a), "l"(g));
}
__device__ __forceinline__ void cp_commit() {
    asm volatile("cp.async.commit_group;\n");
}
template<int N> __device__ __forceinline__ void cp_wait() {
    asm volatile("cp.async.wait_group %0;\n" :: "n"(N));
}

// ---------------------------------------------------------------------------
// Mask preprocessing, full-chip parallel: 512 blocks, each packs a 64-row x
// 256-col patch and computes the 4 covered 64x64 tile flags block-locally.
// ---------------------------------------------------------------------------
__global__ __launch_bounds__(256) void mask_prep2(const int* __restrict__ mask)
{
    __shared__ int flags_s[4];
    const int b  = blockIdx.x;          // 0 .. N_B*32*8-1
    const int n  = b >> 8;
    const int qt = (b >> 3) & 31;
    const int kc = b & 7;               // covers kt = kc*4 .. kc*4+3

    const int tid = threadIdx.x;
    if (tid < 4) flags_s[tid] = 1;
    __syncthreads();

    const int r = tid >> 2;             // 0..63 row within band
    const int j = tid & 3;              // 0..3: which kt tile in this group
    const int row = qt * 64 + r;
    const int w0 = kc * 8 + j * 2;      // two 32-col words per thread

    const int* src = mask + ((size_t)n * L_S + row) * L_S + (size_t)w0 * 32;
    uint32_t* dst = &g_mpack[((size_t)n * L_S + row) * 64 + w0];

    bool allone = true;
    #pragma unroll
    for (int w = 0; w < 2; w++) {
        const int* p = src + w * 32;
        uint32_t bits = 0;
        #pragma unroll
        for (int i = 0; i < 8; i++) {
            int4 v = *(const int4*)(p + i * 4);
            bits |= (v.x != 0 ? 1u : 0u) << (i * 4);
            bits |= (v.y != 0 ? 1u : 0u) << (i * 4 + 1);
            bits |= (v.z != 0 ? 1u : 0u) << (i * 4 + 2);
            bits |= (v.w != 0 ? 1u : 0u) << (i * 4 + 3);
        }
        dst[w] = bits;
        if (bits != 0xFFFFFFFFu) allone = false;
    }
    if (!allone) atomicAnd(&flags_s[j], 0);
    __syncthreads();

    if (tid < 4)
        g_mflag[((size_t)n * 32 + qt) * 32 + kc * 4 + tid]
            = (unsigned char)flags_s[tid];
}

// ---------------------------------------------------------------------------
// Kernel 1: projections via fp16 mma. blockIdx.y: 0=q,1=k,2=v.
// ---------------------------------------------------------------------------
__global__ __launch_bounds__(256) void proj_mma(
    const float* __restrict__ q_in, const float* __restrict__ k_in,
    const float* __restrict__ v_in,
    const float* __restrict__ Wq, const float* __restrict__ Wk,
    const float* __restrict__ Wv)
{
    const float* x; const float* W; __half* out;
    if (blockIdx.y == 0)      { x = q_in; W = Wq; out = g_qp; }
    else if (blockIdx.y == 1) { x = k_in; W = Wk; out = g_kp; }
    else                      { x = v_in; W = Wv; out = g_vp; }
    const float oscale = (blockIdx.y == 0) ? CEXP : 1.0f;

    __shared__ __half Xs[128 * PITCH];
    __shared__ __half Ws[64 * PITCH];

    const int row0 = blockIdx.x * 128;
    const int tid  = threadIdx.x;

    #pragma unroll
    for (int it = 0; it < 4; it++) {
        int idx = tid * 4 + it * 1024;
        int r = idx >> 6, c = idx & 63;
        float4 w4 = *(const float4*)(W + idx);
        *(__half2*)&Ws[r * PITCH + c]     = __floats2half2_rn(w4.x, w4.y);
        *(__half2*)&Ws[r * PITCH + c + 2] = __floats2half2_rn(w4.z, w4.w);
    }
    #pragma unroll
    for (int it = 0; it < 8; it++) {
        int idx = tid * 4 + it * 1024;
        int r = idx >> 6, c = idx & 63;
        int grow = row0 + r;
        int n = grow >> 15, rem = grow & 32767;
        int l = rem >> 4, h = rem & 15;
        float4 v4 = *(const float4*)(x + ((size_t)(n * L_S + l) * EMB + h * HD + c));
        *(__half2*)&Xs[r * PITCH + c]     = __floats2half2_rn(v4.x, v4.y);
        *(__half2*)&Xs[r * PITCH + c + 2] = __floats2half2_rn(v4.z, v4.w);
    }
    __syncthreads();

    const int warp = tid >> 5, lane = tid & 31;
    const int g = lane >> 2, t4 = lane & 3;
    const int mw = warp * 16;
    const int lr = lane & 7, lc = lane >> 3;

    uint32_t a[4][4];
    #pragma unroll
    for (int kc = 0; kc < 4; kc++) {
        a[kc][0] = *(const uint32_t*)&Xs[(mw + g    ) * PITCH + kc * 16 + 2 * t4];
        a[kc][1] = *(const uint32_t*)&Xs[(mw + g + 8) * PITCH + kc * 16 + 2 * t4];
        a[kc][2] = *(const uint32_t*)&Xs[(mw + g    ) * PITCH + kc * 16 + 2 * t4 + 8];
        a[kc][3] = *(const uint32_t*)&Xs[(mw + g + 8) * PITCH + kc * 16 + 2 * t4 + 8];
    }

    float o[8][4];
    #pragma unroll
    for (int nt = 0; nt < 8; nt++) { o[nt][0]=o[nt][1]=o[nt][2]=o[nt][3]=0.f; }

    #pragma unroll
    for (int nt = 0; nt < 8; nt++) {
        #pragma unroll
        for (int kc0 = 0; kc0 < 4; kc0 += 2) {
            uint32_t b0, b1, b2, b3;
            ldsm_x4(b0, b1, b2, b3,
                &Ws[(nt * 8 + lr) * PITCH + kc0 * 16 + lc * 8]);
            mma16816(o[nt], a[kc0][0], a[kc0][1], a[kc0][2], a[kc0][3], b0, b1);
            mma16816(o[nt], a[kc0+1][0], a[kc0+1][1], a[kc0+1][2], a[kc0+1][3], b2, b3);
        }
    }

    #pragma unroll
    for (int nt = 0; nt < 8; nt++) {
        int e = nt * 8 + 2 * t4;
        int grow = row0 + mw + g;
        int n = grow >> 15, rem = grow & 32767;
        int l = rem >> 4, h = rem & 15;
        *(__half2*)(out + ((size_t)(n * NH + h) * L_S + l) * HD + e)
            = __floats2half2_rn(o[nt][0] * oscale, o[nt][1] * oscale);
        grow += 8; n = grow >> 15; rem = grow & 32767; l = rem >> 4; h = rem & 15;
        *(__half2*)(out + ((size_t)(n * NH + h) * L_S + l) * HD + e)
            = __floats2half2_rn(o[nt][2] * oscale, o[nt][3] * oscale);
    }
}

// ---------------------------------------------------------------------------
__global__ __launch_bounds__(256) void wo_cvt(const float* __restrict__ w)
{
    int i = (blockIdx.x * 256 + threadIdx.x) * 4;
    float4 v = *(const float4*)(w + i);
    *(__half2*)(g_woh + i)     = __floats2half2_rn(v.x, v.y);
    *(__half2*)(g_woh + i + 2) = __floats2half2_rn(v.z, v.w);
}

// ---------------------------------------------------------------------------
// Kernel 2: flash attention (R12-validated config): pipelined, (128,4),
// ex2.approx.f16x2 softmax, ones-column row sums.
// ---------------------------------------------------------------------------
__global__ __launch_bounds__(128, 4) void attn11()
{
    extern __shared__ __half sm8[];
    __half* Ks = sm8;                       // 3 slots of 64*PITCH
    __half* Vs = sm8 + 3 * 64 * PITCH;      // 3 slots of 64*PITCH

    const int nh = blockIdx.x;
    const int qt = blockIdx.y;
    const int n  = nh >> 4, h = nh & 15;
    const int q0 = qt * 64;

    const __half* Qg = g_qp + (size_t)nh * L_S * HD;
    const __half* Kg = g_kp + (size_t)nh * L_S * HD;
    const __half* Vg = g_vp + (size_t)nh * L_S * HD;

    const int tid = threadIdx.x;
    const int warp = tid >> 5, lane = tid & 31;
    const int g = lane >> 2, t4 = lane & 3;
    const int mw = warp * 16;
    const int lr = lane & 7, lc = lane >> 3;

    uint32_t qa[4][4];
    {
        const __half* Qr0 = Qg + (size_t)(q0 + mw + g    ) * HD;
        const __half* Qr1 = Qg + (size_t)(q0 + mw + g + 8) * HD;
        #pragma unroll
        for (int kc = 0; kc < 4; kc++) {
            qa[kc][0] = *(const uint32_t*)&Qr0[kc * 16 + 2 * t4];
            qa[kc][1] = *(const uint32_t*)&Qr1[kc * 16 + 2 * t4];
            qa[kc][2] = *(const uint32_t*)&Qr0[kc * 16 + 2 * t4 + 8];
            qa[kc][3] = *(const uint32_t*)&Qr1[kc * 16 + 2 * t4 + 8];
        }
    }

    const unsigned char* flags = g_mflag + ((size_t)n * 32 + qt) * 32;
    const uint32_t* Mp = g_mpack + (size_t)n * L_S * 64;

    auto load_k = [&](int t) {
        __half* dst = Ks + (t % 3) * 64 * PITCH;
        const __half* src = Kg + (size_t)t * 64 * HD;
        #pragma unroll
        for (int it = 0; it < 4; it++) {
            int c = tid + it * 128;
            int r = c >> 3, off = (c & 7) * 8;
            cp16(&dst[r * PITCH + off], &src[(size_t)r * HD + off]);
        }
    };
    auto load_v = [&](int t) {
        __half* dst = Vs + (t % 3) * 64 * PITCH;
        const __half* src = Vg + (size_t)t * 64 * HD;
        #pragma unroll
        for (int it = 0; it < 4; it++) {
            int c = tid + it * 128;
            int r = c >> 3, off = (c & 7) * 8;
            cp16(&dst[r * PITCH + off], &src[(size_t)r * HD + off]);
        }
    };

    auto gemm1 = [&](const __half* Kt, int t, uint32_t (&pout)[4][4]) {
        const bool do_mask = !flags[t];
        uint64_t w0 = 0, w1 = 0;
        if (do_mask) {
            w0 = *(const uint64_t*)&Mp[(size_t)(q0 + mw + g    ) * 64 + t * 2];
            w1 = *(const uint64_t*)&Mp[(size_t)(q0 + mw + g + 8) * 64 + t * 2];
        }
        #pragma unroll
        for (int ntp = 0; ntp < 4; ntp++) {
            const int nt0 = 2 * ntp, nt1 = 2 * ntp + 1;
            float s0[4] = {0.f, 0.f, 0.f, 0.f};
            float s1[4] = {0.f, 0.f, 0.f, 0.f};
            #pragma unroll
            for (int kc0 = 0; kc0 < 4; kc0 += 2) {
                uint32_t b0, b1, b2, b3;
                ldsm_x4(b0, b1, b2, b3,
                    &Kt[(nt0 * 8 + lr) * PITCH + kc0 * 16 + lc * 8]);
                mma16816(s0, qa[kc0][0], qa[kc0][1], qa[kc0][2], qa[kc0][3], b0, b1);
                mma16816(s0, qa[kc0+1][0], qa[kc0+1][1], qa[kc0+1][2], qa[kc0+1][3], b2, b3);
                ldsm_x4(b0, b1, b2, b3,
                    &Kt[(nt1 * 8 + lr) * PITCH + kc0 * 16 + lc * 8]);
                mma16816(s1, qa[kc0][0], qa[kc0][1], qa[kc0][2], qa[kc0][3], b0, b1);
                mma16816(s1, qa[kc0+1][0], qa[kc0+1][1], qa[kc0+1][2], qa[kc0+1][3], b2, b3);
            }
            if (do_mask) {
                int bit0 = nt0 * 8 + 2 * t4;
                int bit1 = nt1 * 8 + 2 * t4;
                if (!((w0 >> bit0) & 1))       s0[0] = -1e30f;
                if (!((w0 >> (bit0 + 1)) & 1)) s0[1] = -1e30f;
                if (!((w1 >> bit0) & 1))       s0[2] = -1e30f;
                if (!((w1 >> (bit0 + 1)) & 1)) s0[3] = -1e30f;
                if (!((w0 >> bit1) & 1))       s1[0] = -1e30f;
                if (!((w0 >> (bit1 + 1)) & 1)) s1[1] = -1e30f;
                if (!((w1 >> bit1) & 1))       s1[2] = -1e30f;
                if (!((w1 >> (bit1 + 1)) & 1)) s1[3] = -1e30f;
            }
            pout[ntp][0] = h2exp2(packh2(s0[0], s0[1]));
            pout[ntp][1] = h2exp2(packh2(s0[2], s0[3]));
            pout[ntp][2] = h2exp2(packh2(s1[0], s1[1]));
            pout[ntp][3] = h2exp2(packh2(s1[2], s1[3]));
        }
    };

    float o[9][4];
    #pragma unroll
    for (int ne = 0; ne < 9; ne++) { o[ne][0]=o[ne][1]=o[ne][2]=o[ne][3]=0.f; }

    auto gemm2 = [&](int kt, const uint32_t (&p)[4][4]) {
        const __half* Vt = Vs + (kt % 3) * 64 * PITCH;
        #pragma unroll
        for (int ne = 0; ne < 9; ne++) {
            #pragma unroll
            for (int kc0 = 0; kc0 < 4; kc0 += 2) {
                uint32_t b0, b1, b2, b3;
                ldsm_x4_t(b0, b1, b2, b3,
                    &Vt[(kc0 * 16 + lane) * PITCH + ne * 8]);
                mma16816(o[ne], p[kc0][0], p[kc0][1], p[kc0][2], p[kc0][3], b0, b1);
                mma16816(o[ne], p[kc0+1][0], p[kc0+1][1], p[kc0+1][2], p[kc0+1][3], b2, b3);
            }
        }
    };

    load_k(0); load_v(0); load_k(1); load_v(1); load_k(2);
    cp_commit();
    {
        __half pad[8];
        pad[0] = __float2half(1.0f);
        #pragma unroll
        for (int i = 1; i < 8; i++) pad[i] = __float2half(0.0f);
        for (int r = tid; r < 3 * 64; r += 128)
            *(uint4*)&Vs[r * PITCH + 64] = *(const uint4*)pad;
    }
    cp_wait<0>();
    __syncthreads();

    uint32_t pa[4][4], pn[4][4];
    gemm1(Ks, 0, pa);

    const int NT = L_S / 64;               // 32, even
    #pragma unroll 1
    for (int kt = 0; kt < NT; kt += 2) {
        cp_wait<2>();
        __syncthreads();
        gemm1(Ks + ((kt + 1) % 3) * 64 * PITCH, kt + 1, pn);
        gemm2(kt, pa);
        if (kt + 2 < NT) load_v(kt + 2);
        cp_commit();
        if (kt + 3 < NT) load_k(kt + 3);
        cp_commit();

        cp_wait<2>();
        __syncthreads();
        if (kt + 2 < NT)
            gemm1(Ks + ((kt + 2) % 3) * 64 * PITCH, kt + 2, pa);
        gemm2(kt + 1, pn);
        if (kt + 3 < NT) load_v(kt + 3);
        cp_commit();
        if (kt + 4 < NT) load_k(kt + 4);
        cp_commit();
    }

    float l0 = __shfl_sync(0xffffffffu, o[8][0], lane & ~3);
    float l1 = __shfl_sync(0xffffffffu, o[8][2], lane & ~3);

    float inv0 = 1.f / l0, inv1 = 1.f / l1;
    int row = q0 + mw + g;
    __half* base0 = g_att + ((size_t)n * L_S + row) * EMB + h * HD;
    __half* base1 = base0 + (size_t)8 * EMB;
    #pragma unroll
    for (int ne = 0; ne < 8; ne++) {
        int e = ne * 8 + 2 * t4;
        *(__half2*)(base0 + e) = __floats2half2_rn(o[ne][0] * inv0, o[ne][1] * inv0);
        *(__half2*)(base1 + e) = __floats2half2_rn(o[ne][2] * inv1, o[ne][3] * inv1);
    }
}

// ---------------------------------------------------------------------------
// Kernel 3: out projection, BM=128 x BN=128 per block, cp.async 2-stage.
// ---------------------------------------------------------------------------
__global__ __launch_bounds__(256) void out_mma3(
    const float* __restrict__ bo, float* __restrict__ out)
{
    extern __shared__ __half sm[];
    __half* As[2] = { sm, sm + 128 * PITCH };
    __half* Bs[2] = { sm + 2 * 128 * PITCH, sm + 3 * 128 * PITCH };

    const int m0 = blockIdx.x * 128;
    const int e0 = blockIdx.y * 128;
    const int tid = threadIdx.x;
    const int warp = tid >> 5, lane = tid & 31;
    const int g = lane >> 2, t4 = lane & 3;
    const int mw = warp * 16;
    const int lr = lane & 7, lc = lane >> 3;

    auto load_ab = [&](int f, int b) {
        const int f0 = f * 64;
        #pragma unroll
        for (int it = 0; it < 4; it++) {
            int c = tid + it * 256;
            int r = c >> 3, off = (c & 7) * 8;
            cp16(&As[b][r * PITCH + off], &g_att[(size_t)(m0 + r) * EMB + f0 + off]);
        }
        #pragma unroll
        for (int it = 0; it < 4; it++) {
            int c = tid + it * 256;
            int r = c >> 3, off = (c & 7) * 8;
            cp16(&Bs[b][r * PITCH + off], &g_woh[(size_t)(e0 + r) * EMB + f0 + off]);
        }
        cp_commit();
    };

    float o[16][4];
    #pragma unroll
    for (int nt = 0; nt < 16; nt++) { o[nt][0]=o[nt][1]=o[nt][2]=o[nt][3]=0.f; }

    load_ab(0, 0);
    load_ab(1, 1);

    const int NF = EMB / 64;
    for (int f = 0; f < NF; f++) {
        const int b = f & 1;
        if (f == NF - 1) cp_wait<0>(); else cp_wait<1>();
        __syncthreads();

        uint32_t a[4][4];
        #pragma unroll
        for (int kc = 0; kc < 4; kc++) {
            ldsm_x4(a[kc][0], a[kc][1], a[kc][2], a[kc][3],
                &As[b][(mw + lr + ((lane >> 3) & 1) * 8) * PITCH
                       + kc * 16 + (lane >> 4) * 8]);
        }
        #pragma unroll
        for (int nt = 0; nt < 16; nt++) {
            #pragma unroll
            for (int kc0 = 0; kc0 < 4; kc0 += 2) {
                uint32_t b0, b1, b2, b3;
                ldsm_x4(b0, b1, b2, b3,
                    &Bs[b][(nt * 8 + lr) * PITCH + kc0 * 16 + lc * 8]);
                mma16816(o[nt], a[kc0][0], a[kc0][1], a[kc0][2], a[kc0][3], b0, b1);
                mma16816(o[nt], a[kc0+1][0], a[kc0+1][1], a[kc0+1][2], a[kc0+1][3], b2, b3);
            }
        }

        __syncthreads();
        if (f + 2 < NF) load_ab(f + 2, b);
    }

    #pragma unroll
    for (int nt = 0; nt < 16; nt++) {
        int e = e0 + nt * 8 + 2 * t4;
        float b0v = bo[e], b1v = bo[e + 1];
        float2* d0 = (float2*)(out + (size_t)(m0 + mw + g    ) * EMB + e);
        float2* d1 = (float2*)(out + (size_t)(m0 + mw + g + 8) * EMB + e);
        *d0 = make_float2(o[nt][0] + b0v, o[nt][1] + b1v);
        *d1 = make_float2(o[nt][2] + b0v, o[nt][3] + b1v);
    }
}

// ---------------------------------------------------------------------------
extern "C" void kernel_launch(void* const* d_in, const int* in_sizes, int n_in,
                              void* d_out, int out_size)
{
    const float* values  = (const float*)d_in[0];
    const float* keys    = (const float*)d_in[1];
    const float* queries = (const float*)d_in[2];
    const int*   mask    = (const int*)  d_in[3];
    const float* Wv      = (const float*)d_in[4];
    const float* Wk      = (const float*)d_in[5];
    const float* Wq      = (const float*)d_in[6];
    const float* Wo      = (const float*)d_in[7];
    const float* bo      = (const float*)d_in[8];
    float* out = (float*)d_out;

    proj_mma<<<dim3(512, 3), 256>>>(queries, keys, values, Wq, Wk, Wv);
    wo_cvt<<<1024, 256>>>(Wo);
    mask_prep2<<<N_B * 32 * 8, 256>>>(mask);

    const int smem_attn = 6 * 64 * PITCH * sizeof(__half);   // 55296 B
    cudaFuncSetAttribute(attn11, cudaFuncAttributeMaxDynamicSharedMemorySize, smem_attn);
    attn11<<<dim3(N_B * NH, L_S / 64), 128, smem_attn>>>();

    const int smem_out = 4 * 128 * PITCH * sizeof(__half);   // 73728 B
    cudaFuncSetAttribute(out_mma3, cudaFuncAttributeMaxDynamicSharedMemorySize, smem_out);
    out_mma3<<<dim3((N_B * L_S) / 128, EMB / 128), 256, smem_out>>>(bo, out);
}

// round 15
// speedup vs baseline: 1.1375x; 1.0100x over previous
#include <cuda_runtime.h>
#include <cuda_fp16.h>
#include <math.h>
#include <stdint.h>

#define N_B 2
#define L_S 2048
#define EMB 1024
#define NH  16
#define HD  64
#define PITCH 72

// log2(e) / sqrt(EMB) — folded into the Q projection output
#define CEXP 0.045084220027780106f

__device__ __align__(128) __half g_qp[N_B * NH * L_S * HD]; // [n,h,l,d] (pre-scaled by CEXP)
__device__ __align__(128) __half g_kp[N_B * NH * L_S * HD];
__device__ __align__(128) __half g_vp[N_B * NH * L_S * HD];
__device__ __align__(128) __half g_att[N_B * L_S * EMB];    // [n,l,e]
__device__ __align__(128) __half g_woh[EMB * EMB];
__device__ __align__(128) uint32_t g_mpack[N_B * L_S * 64]; // packed mask bits
__device__ unsigned char g_mflag[N_B * 32 * 32];            // all-ones flag per 64x64 tile

// ---------------------------------------------------------------------------
__device__ __forceinline__ uint32_t h2exp2(uint32_t x) {
    uint32_t r;
    asm("ex2.approx.f16x2 %0, %1;\n" : "=r"(r) : "r"(x));
    return r;
}

__device__ __forceinline__ void mma16816(float c[4],
    uint32_t a0, uint32_t a1, uint32_t a2, uint32_t a3,
    uint32_t b0, uint32_t b1)
{
    asm volatile(
        "mma.sync.aligned.m16n8k16.row.col.f32.f16.f16.f32 "
        "{%0,%1,%2,%3}, {%4,%5,%6,%7}, {%8,%9}, {%0,%1,%2,%3};\n"
        : "+f"(c[0]), "+f"(c[1]), "+f"(c[2]), "+f"(c[3])
        : "r"(a0), "r"(a1), "r"(a2), "r"(a3), "r"(b0), "r"(b1));
}

__device__ __forceinline__ uint32_t packh2(float a, float b) {
    union { __half2 h2; uint32_t u; } cvt;
    cvt.h2 = __floats2half2_rn(a, b);
    return cvt.u;
}

__device__ __forceinline__ void ldsm_x4(uint32_t& r0, uint32_t& r1,
                                        uint32_t& r2, uint32_t& r3, const __half* p)
{
    uint32_t a = (uint32_t)__cvta_generic_to_shared(p);
    asm volatile("ldmatrix.sync.aligned.m8n8.x4.shared.b16 {%0,%1,%2,%3}, [%4];\n"
                 : "=r"(r0), "=r"(r1), "=r"(r2), "=r"(r3) : "r"(a));
}

__device__ __forceinline__ void ldsm_x4_t(uint32_t& r0, uint32_t& r1,
                                          uint32_t& r2, uint32_t& r3, const __half* p)
{
    uint32_t a = (uint32_t)__cvta_generic_to_shared(p);
    asm volatile("ldmatrix.sync.aligned.m8n8.x4.trans.shared.b16 {%0,%1,%2,%3}, [%4];\n"
                 : "=r"(r0), "=r"(r1), "=r"(r2), "=r"(r3) : "r"(a));
}

__device__ __forceinline__ void cp16(__half* s, const __half* g) {
    uint32_t a = (uint32_t)__cvta_generic_to_shared(s);
    asm volatile("cp.async.cg.shared.global [%0], [%1], 16;\n" :: "r"(a), "l"(g));
}
__device__ __forceinline__ void cp_commit() {
    asm volatile("cp.async.commit_group;\n");
}
template<int N> __device__ __forceinline__ void cp_wait() {
    asm volatile("cp.async.wait_group %0;\n" :: "n"(N));
}

// ---------------------------------------------------------------------------
// Fused prep kernel: blocks [0,1536) projections, [1536,2560) Wo convert,
// [2560,3072) mask pack+flags. One launch; pipes overlap across block types.
// ---------------------------------------------------------------------------
__global__ __launch_bounds__(256) void prep(
    const float* __restrict__ q_in, const float* __restrict__ k_in,
    const float* __restrict__ v_in,
    const float* __restrict__ Wq, const float* __restrict__ Wk,
    const float* __restrict__ Wv, const float* __restrict__ Wo,
    const int* __restrict__ mask)
{
    __shared__ __half Xs[128 * PITCH];
    __shared__ __half Ws[64 * PITCH];
    __shared__ int flags_s[4];

    const int bid = blockIdx.x;
    const int tid = threadIdx.x;

    if (bid >= 2560) {
        // ---- mask pack + per-64x64-tile flags (512 blocks) ----
        const int b  = bid - 2560;
        const int n  = b >> 8;
        const int qt = (b >> 3) & 31;
        const int kc = b & 7;

        if (tid < 4) flags_s[tid] = 1;
        __syncthreads();

        const int r = tid >> 2;
        const int j = tid & 3;
        const int row = qt * 64 + r;
        const int w0 = kc * 8 + j * 2;

        const int* src = mask + ((size_t)n * L_S + row) * L_S + (size_t)w0 * 32;
        uint32_t* dst = &g_mpack[((size_t)n * L_S + row) * 64 + w0];

        bool allone = true;
        #pragma unroll
        for (int w = 0; w < 2; w++) {
            const int* p = src + w * 32;
            uint32_t bits = 0;
            #pragma unroll
            for (int i = 0; i < 8; i++) {
                int4 v = *(const int4*)(p + i * 4);
                bits |= (v.x != 0 ? 1u : 0u) << (i * 4);
                bits |= (v.y != 0 ? 1u : 0u) << (i * 4 + 1);
                bits |= (v.z != 0 ? 1u : 0u) << (i * 4 + 2);
                bits |= (v.w != 0 ? 1u : 0u) << (i * 4 + 3);
            }
            dst[w] = bits;
            if (bits != 0xFFFFFFFFu) allone = false;
        }
        if (!allone) atomicAnd(&flags_s[j], 0);
        __syncthreads();

        if (tid < 4)
            g_mflag[((size_t)n * 32 + qt) * 32 + kc * 4 + tid]
                = (unsigned char)flags_s[tid];
        return;
    }

    if (bid >= 1536) {
        // ---- Wo float -> half (1024 blocks) ----
        int i = ((bid - 1536) * 256 + tid) * 4;
        float4 v = *(const float4*)(Wo + i);
        *(__half2*)(g_woh + i)     = __floats2half2_rn(v.x, v.y);
        *(__half2*)(g_woh + i + 2) = __floats2half2_rn(v.z, v.w);
        return;
    }

    // ---- projections via fp16 mma (1536 blocks: 512 per q/k/v) ----
    const int py = bid >> 9;            // 0=q, 1=k, 2=v
    const int px = bid & 511;
    const float* x; const float* W; __half* out;
    if (py == 0)      { x = q_in; W = Wq; out = g_qp; }
    else if (py == 1) { x = k_in; W = Wk; out = g_kp; }
    else              { x = v_in; W = Wv; out = g_vp; }
    const float oscale = (py == 0) ? CEXP : 1.0f;

    const int row0 = px * 128;

    #pragma unroll
    for (int it = 0; it < 4; it++) {
        int idx = tid * 4 + it * 1024;
        int r = idx >> 6, c = idx & 63;
        float4 w4 = *(const float4*)(W + idx);
        *(__half2*)&Ws[r * PITCH + c]     = __floats2half2_rn(w4.x, w4.y);
        *(__half2*)&Ws[r * PITCH + c + 2] = __floats2half2_rn(w4.z, w4.w);
    }
    #pragma unroll
    for (int it = 0; it < 8; it++) {
        int idx = tid * 4 + it * 1024;
        int r = idx >> 6, c = idx & 63;
        int grow = row0 + r;
        int n = grow >> 15, rem = grow & 32767;
        int l = rem >> 4, h = rem & 15;
        float4 v4 = *(const float4*)(x + ((size_t)(n * L_S + l) * EMB + h * HD + c));
        *(__half2*)&Xs[r * PITCH + c]     = __floats2half2_rn(v4.x, v4.y);
        *(__half2*)&Xs[r * PITCH + c + 2] = __floats2half2_rn(v4.z, v4.w);
    }
    __syncthreads();

    const int warp = tid >> 5, lane = tid & 31;
    const int g = lane >> 2, t4 = lane & 3;
    const int mw = warp * 16;
    const int lr = lane & 7, lc = lane >> 3;

    uint32_t a[4][4];
    #pragma unroll
    for (int kc = 0; kc < 4; kc++) {
        a[kc][0] = *(const uint32_t*)&Xs[(mw + g    ) * PITCH + kc * 16 + 2 * t4];
        a[kc][1] = *(const uint32_t*)&Xs[(mw + g + 8) * PITCH + kc * 16 + 2 * t4];
        a[kc][2] = *(const uint32_t*)&Xs[(mw + g    ) * PITCH + kc * 16 + 2 * t4 + 8];
        a[kc][3] = *(const uint32_t*)&Xs[(mw + g + 8) * PITCH + kc * 16 + 2 * t4 + 8];
    }

    float o[8][4];
    #pragma unroll
    for (int nt = 0; nt < 8; nt++) { o[nt][0]=o[nt][1]=o[nt][2]=o[nt][3]=0.f; }

    #pragma unroll
    for (int nt = 0; nt < 8; nt++) {
        #pragma unroll
        for (int kc0 = 0; kc0 < 4; kc0 += 2) {
            uint32_t b0, b1, b2, b3;
            ldsm_x4(b0, b1, b2, b3,
                &Ws[(nt * 8 + lr) * PITCH + kc0 * 16 + lc * 8]);
            mma16816(o[nt], a[kc0][0], a[kc0][1], a[kc0][2], a[kc0][3], b0, b1);
            mma16816(o[nt], a[kc0+1][0], a[kc0+1][1], a[kc0+1][2], a[kc0+1][3], b2, b3);
        }
    }

    #pragma unroll
    for (int nt = 0; nt < 8; nt++) {
        int e = nt * 8 + 2 * t4;
        int grow = row0 + mw + g;
        int n = grow >> 15, rem = grow & 32767;
        int l = rem >> 4, h = rem & 15;
        *(__half2*)(out + ((size_t)(n * NH + h) * L_S + l) * HD + e)
            = __floats2half2_rn(o[nt][0] * oscale, o[nt][1] * oscale);
        grow += 8; n = grow >> 15; rem = grow & 32767; l = rem >> 4; h = rem & 15;
        *(__half2*)(out + ((size_t)(n * NH + h) * L_S + l) * HD + e)
            = __floats2half2_rn(o[nt][2] * oscale, o[nt][3] * oscale);
    }
}

// ---------------------------------------------------------------------------
// Kernel 2: flash attention (validated config): pipelined, (128,4),
// ex2.approx.f16x2 softmax, ones-column row sums.
// ---------------------------------------------------------------------------
__global__ __launch_bounds__(128, 4) void attn11()
{
    extern __shared__ __half sm8[];
    __half* Ks = sm8;                       // 3 slots of 64*PITCH
    __half* Vs = sm8 + 3 * 64 * PITCH;      // 3 slots of 64*PITCH

    const int nh = blockIdx.x;
    const int qt = blockIdx.y;
    const int n  = nh >> 4, h = nh & 15;
    const int q0 = qt * 64;

    const __half* Qg = g_qp + (size_t)nh * L_S * HD;
    const __half* Kg = g_kp + (size_t)nh * L_S * HD;
    const __half* Vg = g_vp + (size_t)nh * L_S * HD;

    const int tid = threadIdx.x;
    const int warp = tid >> 5, lane = tid & 31;
    const int g = lane >> 2, t4 = lane & 3;
    const int mw = warp * 16;
    const int lr = lane & 7, lc = lane >> 3;

    uint32_t qa[4][4];
    {
        const __half* Qr0 = Qg + (size_t)(q0 + mw + g    ) * HD;
        const __half* Qr1 = Qg + (size_t)(q0 + mw + g + 8) * HD;
        #pragma unroll
        for (int kc = 0; kc < 4; kc++) {
            qa[kc][0] = *(const uint32_t*)&Qr0[kc * 16 + 2 * t4];
            qa[kc][1] = *(const uint32_t*)&Qr1[kc * 16 + 2 * t4];
            qa[kc][2] = *(const uint32_t*)&Qr0[kc * 16 + 2 * t4 + 8];
            qa[kc][3] = *(const uint32_t*)&Qr1[kc * 16 + 2 * t4 + 8];
        }
    }

    const unsigned char* flags = g_mflag + ((size_t)n * 32 + qt) * 32;
    const uint32_t* Mp = g_mpack + (size_t)n * L_S * 64;

    auto load_k = [&](int t) {
        __half* dst = Ks + (t % 3) * 64 * PITCH;
        const __half* src = Kg + (size_t)t * 64 * HD;
        #pragma unroll
        for (int it = 0; it < 4; it++) {
            int c = tid + it * 128;
            int r = c >> 3, off = (c & 7) * 8;
            cp16(&dst[r * PITCH + off], &src[(size_t)r * HD + off]);
        }
    };
    auto load_v = [&](int t) {
        __half* dst = Vs + (t % 3) * 64 * PITCH;
        const __half* src = Vg + (size_t)t * 64 * HD;
        #pragma unroll
        for (int it = 0; it < 4; it++) {
            int c = tid + it * 128;
            int r = c >> 3, off = (c & 7) * 8;
            cp16(&dst[r * PITCH + off], &src[(size_t)r * HD + off]);
        }
    };

    auto gemm1 = [&](const __half* Kt, int t, uint32_t (&pout)[4][4]) {
        const bool do_mask = !flags[t];
        uint64_t w0 = 0, w1 = 0;
        if (do_mask) {
            w0 = *(const uint64_t*)&Mp[(size_t)(q0 + mw + g    ) * 64 + t * 2];
            w1 = *(const uint64_t*)&Mp[(size_t)(q0 + mw + g + 8) * 64 + t * 2];
        }
        #pragma unroll
        for (int ntp = 0; ntp < 4; ntp++) {
            const int nt0 = 2 * ntp, nt1 = 2 * ntp + 1;
            float s0[4] = {0.f, 0.f, 0.f, 0.f};
            float s1[4] = {0.f, 0.f, 0.f, 0.f};
            #pragma unroll
            for (int kc0 = 0; kc0 < 4; kc0 += 2) {
                uint32_t b0, b1, b2, b3;
                ldsm_x4(b0, b1, b2, b3,
                    &Kt[(nt0 * 8 + lr) * PITCH + kc0 * 16 + lc * 8]);
                mma16816(s0, qa[kc0][0], qa[kc0][1], qa[kc0][2], qa[kc0][3], b0, b1);
                mma16816(s0, qa[kc0+1][0], qa[kc0+1][1], qa[kc0+1][2], qa[kc0+1][3], b2, b3);
                ldsm_x4(b0, b1, b2, b3,
                    &Kt[(nt1 * 8 + lr) * PITCH + kc0 * 16 + lc * 8]);
                mma16816(s1, qa[kc0][0], qa[kc0][1], qa[kc0][2], qa[kc0][3], b0, b1);
                mma16816(s1, qa[kc0+1][0], qa[kc0+1][1], qa[kc0+1][2], qa[kc0+1][3], b2, b3);
            }
            if (do_mask) {
                int bit0 = nt0 * 8 + 2 * t4;
                int bit1 = nt1 * 8 + 2 * t4;
                if (!((w0 >> bit0) & 1))       s0[0] = -1e30f;
                if (!((w0 >> (bit0 + 1)) & 1)) s0[1] = -1e30f;
                if (!((w1 >> bit0) & 1))       s0[2] = -1e30f;
                if (!((w1 >> (bit0 + 1)) & 1)) s0[3] = -1e30f;
                if (!((w0 >> bit1) & 1))       s1[0] = -1e30f;
                if (!((w0 >> (bit1 + 1)) & 1)) s1[1] = -1e30f;
                if (!((w1 >> bit1) & 1))       s1[2] = -1e30f;
                if (!((w1 >> (bit1 + 1)) & 1)) s1[3] = -1e30f;
            }
            pout[ntp][0] = h2exp2(packh2(s0[0], s0[1]));
            pout[ntp][1] = h2exp2(packh2(s0[2], s0[3]));
            pout[ntp][2] = h2exp2(packh2(s1[0], s1[1]));
            pout[ntp][3] = h2exp2(packh2(s1[2], s1[3]));
        }
    };

    float o[9][4];
    #pragma unroll
    for (int ne = 0; ne < 9; ne++) { o[ne][0]=o[ne][1]=o[ne][2]=o[ne][3]=0.f; }

    auto gemm2 = [&](int kt, const uint32_t (&p)[4][4]) {
        const __half* Vt = Vs + (kt % 3) * 64 * PITCH;
        #pragma unroll
        for (int ne = 0; ne < 9; ne++) {
            #pragma unroll
            for (int kc0 = 0; kc0 < 4; kc0 += 2) {
                uint32_t b0, b1, b2, b3;
                ldsm_x4_t(b0, b1, b2, b3,
                    &Vt[(kc0 * 16 + lane) * PITCH + ne * 8]);
                mma16816(o[ne], p[kc0][0], p[kc0][1], p[kc0][2], p[kc0][3], b0, b1);
                mma16816(o[ne], p[kc0+1][0], p[kc0+1][1], p[kc0+1][2], p[kc0+1][3], b2, b3);
            }
        }
    };

    load_k(0); load_v(0); load_k(1); load_v(1); load_k(2);
    cp_commit();
    {
        __half pad[8];
        pad[0] = __float2half(1.0f);
        #pragma unroll
        for (int i = 1; i < 8; i++) pad[i] = __float2half(0.0f);
        for (int r = tid; r < 3 * 64; r += 128)
            *(uint4*)&Vs[r * PITCH + 64] = *(const uint4*)pad;
    }
    cp_wait<0>();
    __syncthreads();

    uint32_t pa[4][4], pn[4][4];
    gemm1(Ks, 0, pa);

    const int NT = L_S / 64;               // 32, even
    #pragma unroll 1
    for (int kt = 0; kt < NT; kt += 2) {
        cp_wait<2>();
        __syncthreads();
        gemm1(Ks + ((kt + 1) % 3) * 64 * PITCH, kt + 1, pn);
        gemm2(kt, pa);
        if (kt + 2 < NT) load_v(kt + 2);
        cp_commit();
        if (kt + 3 < NT) load_k(kt + 3);
        cp_commit();

        cp_wait<2>();
        __syncthreads();
        if (kt + 2 < NT)
            gemm1(Ks + ((kt + 2) % 3) * 64 * PITCH, kt + 2, pa);
        gemm2(kt + 1, pn);
        if (kt + 3 < NT) load_v(kt + 3);
        cp_commit();
        if (kt + 4 < NT) load_k(kt + 4);
        cp_commit();
    }

    float l0 = __shfl_sync(0xffffffffu, o[8][0], lane & ~3);
    float l1 = __shfl_sync(0xffffffffu, o[8][2], lane & ~3);

    float inv0 = 1.f / l0, inv1 = 1.f / l1;
    int row = q0 + mw + g;
    __half* base0 = g_att + ((size_t)n * L_S + row) * EMB + h * HD;
    __half* base1 = base0 + (size_t)8 * EMB;
    #pragma unroll
    for (int ne = 0; ne < 8; ne++) {
        int e = ne * 8 + 2 * t4;
        *(__half2*)(base0 + e) = __floats2half2_rn(o[ne][0] * inv0, o[ne][1] * inv0);
        *(__half2*)(base1 + e) = __floats2half2_rn(o[ne][2] * inv1, o[ne][3] * inv1);
    }
}

// ---------------------------------------------------------------------------
// Kernel 3: out projection, BM=128 x BN=128 per block, cp.async 2-stage.
// ---------------------------------------------------------------------------
__global__ __launch_bounds__(256) void out_mma3(
    const float* __restrict__ bo, float* __restrict__ out)
{
    extern __shared__ __half sm[];
    __half* As[2] = { sm, sm + 128 * PITCH };
    __half* Bs[2] = { sm + 2 * 128 * PITCH, sm + 3 * 128 * PITCH };

    const int m0 = blockIdx.x * 128;
    const int e0 = blockIdx.y * 128;
    const int tid = threadIdx.x;
    const int warp = tid >> 5, lane = tid & 31;
    const int g = lane >> 2, t4 = lane & 3;
    const int mw = warp * 16;
    const int lr = lane & 7, lc = lane >> 3;

    auto load_ab = [&](int f, int b) {
        const int f0 = f * 64;
        #pragma unroll
        for (int it = 0; it < 4; it++) {
            int c = tid + it * 256;
            int r = c >> 3, off = (c & 7) * 8;
            cp16(&As[b][r * PITCH + off], &g_att[(size_t)(m0 + r) * EMB + f0 + off]);
        }
        #pragma unroll
        for (int it = 0; it < 4; it++) {
            int c = tid + it * 256;
            int r = c >> 3, off = (c & 7) * 8;
            cp16(&Bs[b][r * PITCH + off], &g_woh[(size_t)(e0 + r) * EMB + f0 + off]);
        }
        cp_commit();
    };

    float o[16][4];
    #pragma unroll
    for (int nt = 0; nt < 16; nt++) { o[nt][0]=o[nt][1]=o[nt][2]=o[nt][3]=0.f; }

    load_ab(0, 0);
    load_ab(1, 1);

    const int NF = EMB / 64;
    for (int f = 0; f < NF; f++) {
        const int b = f & 1;
        if (f == NF - 1) cp_wait<0>(); else cp_wait<1>();
        __syncthreads();

        uint32_t a[4][4];
        #pragma unroll
        for (int kc = 0; kc < 4; kc++) {
            ldsm_x4(a[kc][0], a[kc][1], a[kc][2], a[kc][3],
                &As[b][(mw + lr + ((lane >> 3) & 1) * 8) * PITCH
                       + kc * 16 + (lane >> 4) * 8]);
        }
        #pragma unroll
        for (int nt = 0; nt < 16; nt++) {
            #pragma unroll
            for (int kc0 = 0; kc0 < 4; kc0 += 2) {
                uint32_t b0, b1, b2, b3;
                ldsm_x4(b0, b1, b2, b3,
                    &Bs[b][(nt * 8 + lr) * PITCH + kc0 * 16 + lc * 8]);
                mma16816(o[nt], a[kc0][0], a[kc0][1], a[kc0][2], a[kc0][3], b0, b1);
                mma16816(o[nt], a[kc0+1][0], a[kc0+1][1], a[kc0+1][2], a[kc0+1][3], b2, b3);
            }
        }

        __syncthreads();
        if (f + 2 < NF) load_ab(f + 2, b);
    }

    #pragma unroll
    for (int nt = 0; nt < 16; nt++) {
        int e = e0 + nt * 8 + 2 * t4;
        float b0v = bo[e], b1v = bo[e + 1];
        float2* d0 = (float2*)(out + (size_t)(m0 + mw + g    ) * EMB + e);
        float2* d1 = (float2*)(out + (size_t)(m0 + mw + g + 8) * EMB + e);
        *d0 = make_float2(o[nt][0] + b0v, o[nt][1] + b1v);
        *d1 = make_float2(o[nt][2] + b0v, o[nt][3] + b1v);
    }
}

// ---------------------------------------------------------------------------
extern "C" void kernel_launch(void* const* d_in, const int* in_sizes, int n_in,
                              void* d_out, int out_size)
{
    const float* values  = (const float*)d_in[0];
    const float* keys    = (const float*)d_in[1];
    const float* queries = (const float*)d_in[2];
    const int*   mask    = (const int*)  d_in[3];
    const float* Wv      = (const float*)d_in[4];
    const float* Wk      = (const float*)d_in[5];
    const float* Wq      = (const float*)d_in[6];
    const float* Wo      = (const float*)d_in[7];
    const float* bo      = (const float*)d_in[8];
    float* out = (float*)d_out;

    prep<<<3072, 256>>>(queries, keys, values, Wq, Wk, Wv, Wo, mask);

    const int smem_attn = 6 * 64 * PITCH * sizeof(__half);   // 55296 B
    cudaFuncSetAttribute(attn11, cudaFuncAttributeMaxDynamicSharedMemorySize, smem_attn);
    attn11<<<dim3(N_B * NH, L_S / 64), 128, smem_attn>>>();

    const int smem_out = 4 * 128 * PITCH * sizeof(__half);   // 73728 B
    cudaFuncSetAttribute(out_mma3, cudaFuncAttributeMaxDynamicSharedMemorySize, smem_out);
    out_mma3<<<dim3((N_B * L_S) / 128, EMB / 128), 256, smem_out>>>(bo, out);
}

// round 16
// speedup vs baseline: 1.1507x; 1.0116x over previous
#include <cuda_runtime.h>
#include <cuda_fp16.h>
#include <math.h>
#include <stdint.h>

#define N_B 2
#define L_S 2048
#define EMB 1024
#define NH  16
#define HD  64
#define PITCH 72

// log2(e) / sqrt(EMB) — folded into the Q projection output
#define CEXP 0.045084220027780106f

__device__ __align__(128) __half g_qp[N_B * NH * L_S * HD]; // [n,h,l,d] (pre-scaled by CEXP)
__device__ __align__(128) __half g_kp[N_B * NH * L_S * HD];
__device__ __align__(128) __half g_vp[N_B * NH * L_S * HD];
__device__ __align__(128) __half g_att[N_B * L_S * EMB];    // [n,l,e]
__device__ __align__(128) __half g_woh[EMB * EMB];
__device__ __align__(128) uint32_t g_mpack[N_B * L_S * 64]; // packed mask bits
__device__ unsigned char g_mflag[N_B * 32 * 32];            // all-ones flag per 64x64 tile

// ---------------------------------------------------------------------------
__device__ __forceinline__ uint32_t h2exp2(uint32_t x) {
    uint32_t r;
    asm("ex2.approx.f16x2 %0, %1;\n" : "=r"(r) : "r"(x));
    return r;
}

__device__ __forceinline__ void mma16816(float c[4],
    uint32_t a0, uint32_t a1, uint32_t a2, uint32_t a3,
    uint32_t b0, uint32_t b1)
{
    asm volatile(
        "mma.sync.aligned.m16n8k16.row.col.f32.f16.f16.f32 "
        "{%0,%1,%2,%3}, {%4,%5,%6,%7}, {%8,%9}, {%0,%1,%2,%3};\n"
        : "+f"(c[0]), "+f"(c[1]), "+f"(c[2]), "+f"(c[3])
        : "r"(a0), "r"(a1), "r"(a2), "r"(a3), "r"(b0), "r"(b1));
}

__device__ __forceinline__ uint32_t packh2(float a, float b) {
    union { __half2 h2; uint32_t u; } cvt;
    cvt.h2 = __floats2half2_rn(a, b);
    return cvt.u;
}

__device__ __forceinline__ void ldsm_x4(uint32_t& r0, uint32_t& r1,
                                        uint32_t& r2, uint32_t& r3, const __half* p)
{
    uint32_t a = (uint32_t)__cvta_generic_to_shared(p);
    asm volatile("ldmatrix.sync.aligned.m8n8.x4.shared.b16 {%0,%1,%2,%3}, [%4];\n"
                 : "=r"(r0), "=r"(r1), "=r"(r2), "=r"(r3) : "r"(a));
}

__device__ __forceinline__ void ldsm_x4_t(uint32_t& r0, uint32_t& r1,
                                          uint32_t& r2, uint32_t& r3, const __half* p)
{
    uint32_t a = (uint32_t)__cvta_generic_to_shared(p);
    asm volatile("ldmatrix.sync.aligned.m8n8.x4.trans.shared.b16 {%0,%1,%2,%3}, [%4];\n"
                 : "=r"(r0), "=r"(r1), "=r"(r2), "=r"(r3) : "r"(a));
}

__device__ __forceinline__ void cp16(__half* s, const __half* g) {
    uint32_t a = (uint32_t)__cvta_generic_to_shared(s);
    asm volatile("cp.async.cg.shared.global [%0], [%1], 16;\n" :: "r"(a), "l"(g));
}
__device__ __forceinline__ void cp_commit() {
    asm volatile("cp.async.commit_group;\n");
}
template<int N> __device__ __forceinline__ void cp_wait() {
    asm volatile("cp.async.wait_group %0;\n" :: "n"(N));
}

// ---------------------------------------------------------------------------
// Fused prep kernel, WAVE-INTERLEAVED: each group of 6 consecutive block ids
// contains 3 projection blocks, 2 Wo-convert blocks, 1 mask block, so every
// scheduling wave carries the same 3:2:1 mix of tensor/copy/DRAM work.
// ---------------------------------------------------------------------------
__global__ __launch_bounds__(256) void prep(
    const float* __restrict__ q_in, const float* __restrict__ k_in,
    const float* __restrict__ v_in,
    const float* __restrict__ Wq, const float* __restrict__ Wk,
    const float* __restrict__ Wv, const float* __restrict__ Wo,
    const int* __restrict__ mask)
{
    __shared__ __half Xs[128 * PITCH];
    __shared__ __half Ws[64 * PITCH];
    __shared__ int flags_s[4];

    const int grp = blockIdx.x / 6;     // 0..511
    const int sub = blockIdx.x % 6;     // 0,1,2=proj  3,4=wo  5=mask
    const int tid = threadIdx.x;

    if (sub == 5) {
        // ---- mask pack + per-64x64-tile flags (512 blocks) ----
        const int b  = grp;
        const int n  = b >> 8;
        const int qt = (b >> 3) & 31;
        const int kc = b & 7;

        if (tid < 4) flags_s[tid] = 1;
        __syncthreads();

        const int r = tid >> 2;
        const int j = tid & 3;
        const int row = qt * 64 + r;
        const int w0 = kc * 8 + j * 2;

        const int* src = mask + ((size_t)n * L_S + row) * L_S + (size_t)w0 * 32;
        uint32_t* dst = &g_mpack[((size_t)n * L_S + row) * 64 + w0];

        bool allone = true;
        #pragma unroll
        for (int w = 0; w < 2; w++) {
            const int* p = src + w * 32;
            uint32_t bits = 0;
            #pragma unroll
            for (int i = 0; i < 8; i++) {
                int4 v = *(const int4*)(p + i * 4);
                bits |= (v.x != 0 ? 1u : 0u) << (i * 4);
                bits |= (v.y != 0 ? 1u : 0u) << (i * 4 + 1);
                bits |= (v.z != 0 ? 1u : 0u) << (i * 4 + 2);
                bits |= (v.w != 0 ? 1u : 0u) << (i * 4 + 3);
            }
            dst[w] = bits;
            if (bits != 0xFFFFFFFFu) allone = false;
        }
        if (!allone) atomicAnd(&flags_s[j], 0);
        __syncthreads();

        if (tid < 4)
            g_mflag[((size_t)n * 32 + qt) * 32 + kc * 4 + tid]
                = (unsigned char)flags_s[tid];
        return;
    }

    if (sub >= 3) {
        // ---- Wo float -> half (1024 blocks) ----
        int wb = grp * 2 + (sub - 3);
        int i = (wb * 256 + tid) * 4;
        float4 v = *(const float4*)(Wo + i);
        *(__half2*)(g_woh + i)     = __floats2half2_rn(v.x, v.y);
        *(__half2*)(g_woh + i + 2) = __floats2half2_rn(v.z, v.w);
        return;
    }

    // ---- projections via fp16 mma (1536 blocks) ----
    const int pidx = grp * 3 + sub;     // 0..1535
    const int py = pidx >> 9;           // 0=q, 1=k, 2=v
    const int px = pidx & 511;
    const float* x; const float* W; __half* out;
    if (py == 0)      { x = q_in; W = Wq; out = g_qp; }
    else if (py == 1) { x = k_in; W = Wk; out = g_kp; }
    else              { x = v_in; W = Wv; out = g_vp; }
    const float oscale = (py == 0) ? CEXP : 1.0f;

    const int row0 = px * 128;

    #pragma unroll
    for (int it = 0; it < 4; it++) {
        int idx = tid * 4 + it * 1024;
        int r = idx >> 6, c = idx & 63;
        float4 w4 = *(const float4*)(W + idx);
        *(__half2*)&Ws[r * PITCH + c]     = __floats2half2_rn(w4.x, w4.y);
        *(__half2*)&Ws[r * PITCH + c + 2] = __floats2half2_rn(w4.z, w4.w);
    }
    #pragma unroll
    for (int it = 0; it < 8; it++) {
        int idx = tid * 4 + it * 1024;
        int r = idx >> 6, c = idx & 63;
        int grow = row0 + r;
        int n = grow >> 15, rem = grow & 32767;
        int l = rem >> 4, h = rem & 15;
        float4 v4 = *(const float4*)(x + ((size_t)(n * L_S + l) * EMB + h * HD + c));
        *(__half2*)&Xs[r * PITCH + c]     = __floats2half2_rn(v4.x, v4.y);
        *(__half2*)&Xs[r * PITCH + c + 2] = __floats2half2_rn(v4.z, v4.w);
    }
    __syncthreads();

    const int warp = tid >> 5, lane = tid & 31;
    const int g = lane >> 2, t4 = lane & 3;
    const int mw = warp * 16;
    const int lr = lane & 7, lc = lane >> 3;

    uint32_t a[4][4];
    #pragma unroll
    for (int kc = 0; kc < 4; kc++) {
        a[kc][0] = *(const uint32_t*)&Xs[(mw + g    ) * PITCH + kc * 16 + 2 * t4];
        a[kc][1] = *(const uint32_t*)&Xs[(mw + g + 8) * PITCH + kc * 16 + 2 * t4];
        a[kc][2] = *(const uint32_t*)&Xs[(mw + g    ) * PITCH + kc * 16 + 2 * t4 + 8];
        a[kc][3] = *(const uint32_t*)&Xs[(mw + g + 8) * PITCH + kc * 16 + 2 * t4 + 8];
    }

    float o[8][4];
    #pragma unroll
    for (int nt = 0; nt < 8; nt++) { o[nt][0]=o[nt][1]=o[nt][2]=o[nt][3]=0.f; }

    #pragma unroll
    for (int nt = 0; nt < 8; nt++) {
        #pragma unroll
        for (int kc0 = 0; kc0 < 4; kc0 += 2) {
            uint32_t b0, b1, b2, b3;
            ldsm_x4(b0, b1, b2, b3,
                &Ws[(nt * 8 + lr) * PITCH + kc0 * 16 + lc * 8]);
            mma16816(o[nt], a[kc0][0], a[kc0][1], a[kc0][2], a[kc0][3], b0, b1);
            mma16816(o[nt], a[kc0+1][0], a[kc0+1][1], a[kc0+1][2], a[kc0+1][3], b2, b3);
        }
    }

    #pragma unroll
    for (int nt = 0; nt < 8; nt++) {
        int e = nt * 8 + 2 * t4;
        int grow = row0 + mw + g;
        int n = grow >> 15, rem = grow & 32767;
        int l = rem >> 4, h = rem & 15;
        *(__half2*)(out + ((size_t)(n * NH + h) * L_S + l) * HD + e)
            = __floats2half2_rn(o[nt][0] * oscale, o[nt][1] * oscale);
        grow += 8; n = grow >> 15; rem = grow & 32767; l = rem >> 4; h = rem & 15;
        *(__half2*)(out + ((size_t)(n * NH + h) * L_S + l) * HD + e)
            = __floats2half2_rn(o[nt][2] * oscale, o[nt][3] * oscale);
    }
}

// ---------------------------------------------------------------------------
// Kernel 2: flash attention (validated config): pipelined, (128,4),
// ex2.approx.f16x2 softmax, ones-column row sums.
// ---------------------------------------------------------------------------
__global__ __launch_bounds__(128, 4) void attn11()
{
    extern __shared__ __half sm8[];
    __half* Ks = sm8;                       // 3 slots of 64*PITCH
    __half* Vs = sm8 + 3 * 64 * PITCH;      // 3 slots of 64*PITCH

    const int nh = blockIdx.x;
    const int qt = blockIdx.y;
    const int n  = nh >> 4, h = nh & 15;
    const int q0 = qt * 64;

    const __half* Qg = g_qp + (size_t)nh * L_S * HD;
    const __half* Kg = g_kp + (size_t)nh * L_S * HD;
    const __half* Vg = g_vp + (size_t)nh * L_S * HD;

    const int tid = threadIdx.x;
    const int warp = tid >> 5, lane = tid & 31;
    const int g = lane >> 2, t4 = lane & 3;
    const int mw = warp * 16;
    const int lr = lane & 7, lc = lane >> 3;

    uint32_t qa[4][4];
    {
        const __half* Qr0 = Qg + (size_t)(q0 + mw + g    ) * HD;
        const __half* Qr1 = Qg + (size_t)(q0 + mw + g + 8) * HD;
        #pragma unroll
        for (int kc = 0; kc < 4; kc++) {
            qa[kc][0] = *(const uint32_t*)&Qr0[kc * 16 + 2 * t4];
            qa[kc][1] = *(const uint32_t*)&Qr1[kc * 16 + 2 * t4];
            qa[kc][2] = *(const uint32_t*)&Qr0[kc * 16 + 2 * t4 + 8];
            qa[kc][3] = *(const uint32_t*)&Qr1[kc * 16 + 2 * t4 + 8];
        }
    }

    const unsigned char* flags = g_mflag + ((size_t)n * 32 + qt) * 32;
    const uint32_t* Mp = g_mpack + (size_t)n * L_S * 64;

    auto load_k = [&](int t) {
        __half* dst = Ks + (t % 3) * 64 * PITCH;
        const __half* src = Kg + (size_t)t * 64 * HD;
        #pragma unroll
        for (int it = 0; it < 4; it++) {
            int c = tid + it * 128;
            int r = c >> 3, off = (c & 7) * 8;
            cp16(&dst[r * PITCH + off], &src[(size_t)r * HD + off]);
        }
    };
    auto load_v = [&](int t) {
        __half* dst = Vs + (t % 3) * 64 * PITCH;
        const __half* src = Vg + (size_t)t * 64 * HD;
        #pragma unroll
        for (int it = 0; it < 4; it++) {
            int c = tid + it * 128;
            int r = c >> 3, off = (c & 7) * 8;
            cp16(&dst[r * PITCH + off], &src[(size_t)r * HD + off]);
        }
    };

    auto gemm1 = [&](const __half* Kt, int t, uint32_t (&pout)[4][4]) {
        const bool do_mask = !flags[t];
        uint64_t w0 = 0, w1 = 0;
        if (do_mask) {
            w0 = *(const uint64_t*)&Mp[(size_t)(q0 + mw + g    ) * 64 + t * 2];
            w1 = *(const uint64_t*)&Mp[(size_t)(q0 + mw + g + 8) * 64 + t * 2];
        }
        #pragma unroll
        for (int ntp = 0; ntp < 4; ntp++) {
            const int nt0 = 2 * ntp, nt1 = 2 * ntp + 1;
            float s0[4] = {0.f, 0.f, 0.f, 0.f};
            float s1[4] = {0.f, 0.f, 0.f, 0.f};
            #pragma unroll
            for (int kc0 = 0; kc0 < 4; kc0 += 2) {
                uint32_t b0, b1, b2, b3;
                ldsm_x4(b0, b1, b2, b3,
                    &Kt[(nt0 * 8 + lr) * PITCH + kc0 * 16 + lc * 8]);
                mma16816(s0, qa[kc0][0], qa[kc0][1], qa[kc0][2], qa[kc0][3], b0, b1);
                mma16816(s0, qa[kc0+1][0], qa[kc0+1][1], qa[kc0+1][2], qa[kc0+1][3], b2, b3);
                ldsm_x4(b0, b1, b2, b3,
                    &Kt[(nt1 * 8 + lr) * PITCH + kc0 * 16 + lc * 8]);
                mma16816(s1, qa[kc0][0], qa[kc0][1], qa[kc0][2], qa[kc0][3], b0, b1);
                mma16816(s1, qa[kc0+1][0], qa[kc0+1][1], qa[kc0+1][2], qa[kc0+1][3], b2, b3);
            }
            if (do_mask) {
                int bit0 = nt0 * 8 + 2 * t4;
                int bit1 = nt1 * 8 + 2 * t4;
                if (!((w0 >> bit0) & 1))       s0[0] = -1e30f;
                if (!((w0 >> (bit0 + 1)) & 1)) s0[1] = -1e30f;
                if (!((w1 >> bit0) & 1))       s0[2] = -1e30f;
                if (!((w1 >> (bit0 + 1)) & 1)) s0[3] = -1e30f;
                if (!((w0 >> bit1) & 1))       s1[0] = -1e30f;
                if (!((w0 >> (bit1 + 1)) & 1)) s1[1] = -1e30f;
                if (!((w1 >> bit1) & 1))       s1[2] = -1e30f;
                if (!((w1 >> (bit1 + 1)) & 1)) s1[3] = -1e30f;
            }
            pout[ntp][0] = h2exp2(packh2(s0[0], s0[1]));
            pout[ntp][1] = h2exp2(packh2(s0[2], s0[3]));
            pout[ntp][2] = h2exp2(packh2(s1[0], s1[1]));
            pout[ntp][3] = h2exp2(packh2(s1[2], s1[3]));
        }
    };

    float o[9][4];
    #pragma unroll
    for (int ne = 0; ne < 9; ne++) { o[ne][0]=o[ne][1]=o[ne][2]=o[ne][3]=0.f; }

    auto gemm2 = [&](int kt, const uint32_t (&p)[4][4]) {
        const __half* Vt = Vs + (kt % 3) * 64 * PITCH;
        #pragma unroll
        for (int ne = 0; ne < 9; ne++) {
            #pragma unroll
            for (int kc0 = 0; kc0 < 4; kc0 += 2) {
                uint32_t b0, b1, b2, b3;
                ldsm_x4_t(b0, b1, b2, b3,
                    &Vt[(kc0 * 16 + lane) * PITCH + ne * 8]);
                mma16816(o[ne], p[kc0][0], p[kc0][1], p[kc0][2], p[kc0][3], b0, b1);
                mma16816(o[ne], p[kc0+1][0], p[kc0+1][1], p[kc0+1][2], p[kc0+1][3], b2, b3);
            }
        }
    };

    load_k(0); load_v(0); load_k(1); load_v(1); load_k(2);
    cp_commit();
    {
        __half pad[8];
        pad[0] = __float2half(1.0f);
        #pragma unroll
        for (int i = 1; i < 8; i++) pad[i] = __float2half(0.0f);
        for (int r = tid; r < 3 * 64; r += 128)
            *(uint4*)&Vs[r * PITCH + 64] = *(const uint4*)pad;
    }
    cp_wait<0>();
    __syncthreads();

    uint32_t pa[4][4], pn[4][4];
    gemm1(Ks, 0, pa);

    const int NT = L_S / 64;               // 32, even
    #pragma unroll 1
    for (int kt = 0; kt < NT; kt += 2) {
        cp_wait<2>();
        __syncthreads();
        gemm1(Ks + ((kt + 1) % 3) * 64 * PITCH, kt + 1, pn);
        gemm2(kt, pa);
        if (kt + 2 < NT) load_v(kt + 2);
        cp_commit();
        if (kt + 3 < NT) load_k(kt + 3);
        cp_commit();

        cp_wait<2>();
        __syncthreads();
        if (kt + 2 < NT)
            gemm1(Ks + ((kt + 2) % 3) * 64 * PITCH, kt + 2, pa);
        gemm2(kt + 1, pn);
        if (kt + 3 < NT) load_v(kt + 3);
        cp_commit();
        if (kt + 4 < NT) load_k(kt + 4);
        cp_commit();
    }

    float l0 = __shfl_sync(0xffffffffu, o[8][0], lane & ~3);
    float l1 = __shfl_sync(0xffffffffu, o[8][2], lane & ~3);

    float inv0 = 1.f / l0, inv1 = 1.f / l1;
    int row = q0 + mw + g;
    __half* base0 = g_att + ((size_t)n * L_S + row) * EMB + h * HD;
    __half* base1 = base0 + (size_t)8 * EMB;
    #pragma unroll
    for (int ne = 0; ne < 8; ne++) {
        int e = ne * 8 + 2 * t4;
        *(__half2*)(base0 + e) = __floats2half2_rn(o[ne][0] * inv0, o[ne][1] * inv0);
        *(__half2*)(base1 + e) = __floats2half2_rn(o[ne][2] * inv1, o[ne][3] * inv1);
    }
}

// ---------------------------------------------------------------------------
// Kernel 3: out projection, BM=128 x BN=128 per block, cp.async 2-stage.
// ---------------------------------------------------------------------------
__global__ __launch_bounds__(256) void out_mma3(
    const float* __restrict__ bo, float* __restrict__ out)
{
    extern __shared__ __half sm[];
    __half* As[2] = { sm, sm + 128 * PITCH };
    __half* Bs[2] = { sm + 2 * 128 * PITCH, sm + 3 * 128 * PITCH };

    const int m0 = blockIdx.x * 128;
    const int e0 = blockIdx.y * 128;
    const int tid = threadIdx.x;
    const int warp = tid >> 5, lane = tid & 31;
    const int g = lane >> 2, t4 = lane & 3;
    const int mw = warp * 16;
    const int lr = lane & 7, lc = lane >> 3;

    auto load_ab = [&](int f, int b) {
        const int f0 = f * 64;
        #pragma unroll
        for (int it = 0; it < 4; it++) {
            int c = tid + it * 256;
            int r = c >> 3, off = (c & 7) * 8;
            cp16(&As[b][r * PITCH + off], &g_att[(size_t)(m0 + r) * EMB + f0 + off]);
        }
        #pragma unroll
        for (int it = 0; it < 4; it++) {
            int c = tid + it * 256;
            int r = c >> 3, off = (c & 7) * 8;
            cp16(&Bs[b][r * PITCH + off], &g_woh[(size_t)(e0 + r) * EMB + f0 + off]);
        }
        cp_commit();
    };

    float o[16][4];
    #pragma unroll
    for (int nt = 0; nt < 16; nt++) { o[nt][0]=o[nt][1]=o[nt][2]=o[nt][3]=0.f; }

    load_ab(0, 0);
    load_ab(1, 1);

    const int NF = EMB / 64;
    for (int f = 0; f < NF; f++) {
        const int b = f & 1;
        if (f == NF - 1) cp_wait<0>(); else cp_wait<1>();
        __syncthreads();

        uint32_t a[4][4];
        #pragma unroll
        for (int kc = 0; kc < 4; kc++) {
            ldsm_x4(a[kc][0], a[kc][1], a[kc][2], a[kc][3],
                &As[b][(mw + lr + ((lane >> 3) & 1) * 8) * PITCH
                       + kc * 16 + (lane >> 4) * 8]);
        }
        #pragma unroll
        for (int nt = 0; nt < 16; nt++) {
            #pragma unroll
            for (int kc0 = 0; kc0 < 4; kc0 += 2) {
                uint32_t b0, b1, b2, b3;
                ldsm_x4(b0, b1, b2, b3,
                    &Bs[b][(nt * 8 + lr) * PITCH + kc0 * 16 + lc * 8]);
                mma16816(o[nt], a[kc0][0], a[kc0][1], a[kc0][2], a[kc0][3], b0, b1);
                mma16816(o[nt], a[kc0+1][0], a[kc0+1][1], a[kc0+1][2], a[kc0+1][3], b2, b3);
            }
        }

        __syncthreads();
        if (f + 2 < NF) load_ab(f + 2, b);
    }

    #pragma unroll
    for (int nt = 0; nt < 16; nt++) {
        int e = e0 + nt * 8 + 2 * t4;
        float b0v = bo[e], b1v = bo[e + 1];
        float2* d0 = (float2*)(out + (size_t)(m0 + mw + g    ) * EMB + e);
        float2* d1 = (float2*)(out + (size_t)(m0 + mw + g + 8) * EMB + e);
        *d0 = make_float2(o[nt][0] + b0v, o[nt][1] + b1v);
        *d1 = make_float2(o[nt][2] + b0v, o[nt][3] + b1v);
    }
}

// ---------------------------------------------------------------------------
extern "C" void kernel_launch(void* const* d_in, const int* in_sizes, int n_in,
                              void* d_out, int out_size)
{
    const float* values  = (const float*)d_in[0];
    const float* keys    = (const float*)d_in[1];
    const float* queries = (const float*)d_in[2];
    const int*   mask    = (const int*)  d_in[3];
    const float* Wv      = (const float*)d_in[4];
    const float* Wk      = (const float*)d_in[5];
    const float* Wq      = (const float*)d_in[6];
    const float* Wo      = (const float*)d_in[7];
    const float* bo      = (const float*)d_in[8];
    float* out = (float*)d_out;

    prep<<<3072, 256>>>(queries, keys, values, Wq, Wk, Wv, Wo, mask);

    const int smem_attn = 6 * 64 * PITCH * sizeof(__half);   // 55296 B
    cudaFuncSetAttribute(attn11, cudaFuncAttributeMaxDynamicSharedMemorySize, smem_attn);
    attn11<<<dim3(N_B * NH, L_S / 64), 128, smem_attn>>>();

    const int smem_out = 4 * 128 * PITCH * sizeof(__half);   // 73728 B
    cudaFuncSetAttribute(out_mma3, cudaFuncAttributeMaxDynamicSharedMemorySize, smem_out);
    out_mma3<<<dim3((N_B * L_S) / 128, EMB / 128), 256, smem_out>>>(bo, out);
}

// round 17
// speedup vs baseline: 1.1595x; 1.0076x over previous
#include <cuda_runtime.h>
#include <cuda_fp16.h>
#include <math.h>
#include <stdint.h>

#define N_B 2
#define L_S 2048
#define EMB 1024
#define NH  16
#define HD  64
#define PITCH 72

// log2(e) / sqrt(EMB) — folded into the Q projection output
#define CEXP 0.045084220027780106f

__device__ __align__(128) __half g_qp[N_B * NH * L_S * HD]; // [n,h,l,d] (pre-scaled by CEXP)
__device__ __align__(128) __half g_kp[N_B * NH * L_S * HD];
__device__ __align__(128) __half g_vp[N_B * NH * L_S * HD];
__device__ __align__(128) __half g_att[N_B * L_S * EMB];    // [n,l,e]
__device__ __align__(128) __half g_woh[EMB * EMB];
__device__ __align__(128) uint32_t g_mpack[N_B * L_S * 64]; // packed mask bits
__device__ unsigned char g_mflag[N_B * 32 * 32];            // all-ones flag per 64x64 tile

// ---------------------------------------------------------------------------
__device__ __forceinline__ uint32_t h2exp2(uint32_t x) {
    uint32_t r;
    asm("ex2.approx.f16x2 %0, %1;\n" : "=r"(r) : "r"(x));
    return r;
}

__device__ __forceinline__ void mma16816(float c[4],
    uint32_t a0, uint32_t a1, uint32_t a2, uint32_t a3,
    uint32_t b0, uint32_t b1)
{
    asm volatile(
        "mma.sync.aligned.m16n8k16.row.col.f32.f16.f16.f32 "
        "{%0,%1,%2,%3}, {%4,%5,%6,%7}, {%8,%9}, {%0,%1,%2,%3};\n"
        : "+f"(c[0]), "+f"(c[1]), "+f"(c[2]), "+f"(c[3])
        : "r"(a0), "r"(a1), "r"(a2), "r"(a3), "r"(b0), "r"(b1));
}

__device__ __forceinline__ uint32_t packh2(float a, float b) {
    union { __half2 h2; uint32_t u; } cvt;
    cvt.h2 = __floats2half2_rn(a, b);
    return cvt.u;
}

__device__ __forceinline__ __half2 u2h2(uint32_t u) {
    union { uint32_t u; __half2 h2; } cvt;
    cvt.u = u;
    return cvt.h2;
}

__device__ __forceinline__ void ldsm_x4(uint32_t& r0, uint32_t& r1,
                                        uint32_t& r2, uint32_t& r3, const __half* p)
{
    uint32_t a = (uint32_t)__cvta_generic_to_shared(p);
    asm volatile("ldmatrix.sync.aligned.m8n8.x4.shared.b16 {%0,%1,%2,%3}, [%4];\n"
                 : "=r"(r0), "=r"(r1), "=r"(r2), "=r"(r3) : "r"(a));
}

__device__ __forceinline__ void ldsm_x4_t(uint32_t& r0, uint32_t& r1,
                                          uint32_t& r2, uint32_t& r3, const __half* p)
{
    uint32_t a = (uint32_t)__cvta_generic_to_shared(p);
    asm volatile("ldmatrix.sync.aligned.m8n8.x4.trans.shared.b16 {%0,%1,%2,%3}, [%4];\n"
                 : "=r"(r0), "=r"(r1), "=r"(r2), "=r"(r3) : "r"(a));
}

__device__ __forceinline__ void cp16(__half* s, const __half* g) {
    uint32_t a = (uint32_t)__cvta_generic_to_shared(s);
    asm volatile("cp.async.cg.shared.global [%0], [%1], 16;\n" :: "r"(a), "l"(g));
}
__device__ __forceinline__ void cp_commit() {
    asm volatile("cp.async.commit_group;\n");
}
template<int N> __device__ __forceinline__ void cp_wait() {
    asm volatile("cp.async.wait_group %0;\n" :: "n"(N));
}

// ---------------------------------------------------------------------------
// Fused prep kernel (wave-interleaved 3:2:1). Proj path builds X A-fragments
// directly from gmem (no X smem round-trip, shorter latency chain).
// ---------------------------------------------------------------------------
__global__ __launch_bounds__(256) void prep(
    const float* __restrict__ q_in, const float* __restrict__ k_in,
    const float* __restrict__ v_in,
    const float* __restrict__ Wq, const float* __restrict__ Wk,
    const float* __restrict__ Wv, const float* __restrict__ Wo,
    const int* __restrict__ mask)
{
    __shared__ __half Ws[64 * PITCH];
    __shared__ int flags_s[4];

    const int grp = blockIdx.x / 6;     // 0..511
    const int sub = blockIdx.x % 6;     // 0,1,2=proj  3,4=wo  5=mask
    const int tid = threadIdx.x;

    if (sub == 5) {
        // ---- mask pack + per-64x64-tile flags (512 blocks) ----
        const int b  = grp;
        const int n  = b >> 8;
        const int qt = (b >> 3) & 31;
        const int kc = b & 7;

        if (tid < 4) flags_s[tid] = 1;
        __syncthreads();

        const int r = tid >> 2;
        const int j = tid & 3;
        const int row = qt * 64 + r;
        const int w0 = kc * 8 + j * 2;

        const int* src = mask + ((size_t)n * L_S + row) * L_S + (size_t)w0 * 32;
        uint32_t* dst = &g_mpack[((size_t)n * L_S + row) * 64 + w0];

        bool allone = true;
        #pragma unroll
        for (int w = 0; w < 2; w++) {
            const int* p = src + w * 32;
            uint32_t bits = 0;
            #pragma unroll
            for (int i = 0; i < 8; i++) {
                int4 v = *(const int4*)(p + i * 4);
                bits |= (v.x != 0 ? 1u : 0u) << (i * 4);
                bits |= (v.y != 0 ? 1u : 0u) << (i * 4 + 1);
                bits |= (v.z != 0 ? 1u : 0u) << (i * 4 + 2);
                bits |= (v.w != 0 ? 1u : 0u) << (i * 4 + 3);
            }
            dst[w] = bits;
            if (bits != 0xFFFFFFFFu) allone = false;
        }
        if (!allone) atomicAnd(&flags_s[j], 0);
        __syncthreads();

        if (tid < 4)
            g_mflag[((size_t)n * 32 + qt) * 32 + kc * 4 + tid]
                = (unsigned char)flags_s[tid];
        return;
    }

    if (sub >= 3) {
        // ---- Wo float -> half (1024 blocks) ----
        int wb = grp * 2 + (sub - 3);
        int i = (wb * 256 + tid) * 4;
        float4 v = *(const float4*)(Wo + i);
        *(__half2*)(g_woh + i)     = __floats2half2_rn(v.x, v.y);
        *(__half2*)(g_woh + i + 2) = __floats2half2_rn(v.z, v.w);
        return;
    }

    // ---- projections via fp16 mma (1536 blocks) ----
    const int pidx = grp * 3 + sub;     // 0..1535
    const int py = pidx >> 9;           // 0=q, 1=k, 2=v
    const int px = pidx & 511;
    const float* x; const float* W; __half* out;
    if (py == 0)      { x = q_in; W = Wq; out = g_qp; }
    else if (py == 1) { x = k_in; W = Wk; out = g_kp; }
    else              { x = v_in; W = Wv; out = g_vp; }
    const float oscale = (py == 0) ? CEXP : 1.0f;

    const int row0 = px * 128;

    #pragma unroll
    for (int it = 0; it < 4; it++) {
        int idx = tid * 4 + it * 1024;
        int r = idx >> 6, c = idx & 63;
        float4 w4 = *(const float4*)(W + idx);
        *(__half2*)&Ws[r * PITCH + c]     = __floats2half2_rn(w4.x, w4.y);
        *(__half2*)&Ws[r * PITCH + c + 2] = __floats2half2_rn(w4.z, w4.w);
    }

    const int warp = tid >> 5, lane = tid & 31;
    const int g = lane >> 2, t4 = lane & 3;
    const int mw = warp * 16;
    const int lr = lane & 7, lc = lane >> 3;

    // X A-fragments directly from gmem (overlaps with W smem fill)
    uint32_t a[4][4];
    {
        int grow0 = row0 + mw + g;
        int n0 = grow0 >> 15, rem0 = grow0 & 32767;
        const float* X0 = x + ((size_t)(n0 * L_S + (rem0 >> 4)) * EMB
                               + (rem0 & 15) * HD);
        int grow1 = grow0 + 8;
        int n1 = grow1 >> 15, rem1 = grow1 & 32767;
        const float* X1 = x + ((size_t)(n1 * L_S + (rem1 >> 4)) * EMB
                               + (rem1 & 15) * HD);
        #pragma unroll
        for (int kc = 0; kc < 4; kc++) {
            float2 v00 = *(const float2*)&X0[kc * 16 + 2 * t4];
            float2 v10 = *(const float2*)&X1[kc * 16 + 2 * t4];
            float2 v01 = *(const float2*)&X0[kc * 16 + 2 * t4 + 8];
            float2 v11 = *(const float2*)&X1[kc * 16 + 2 * t4 + 8];
            a[kc][0] = packh2(v00.x, v00.y);
            a[kc][1] = packh2(v10.x, v10.y);
            a[kc][2] = packh2(v01.x, v01.y);
            a[kc][3] = packh2(v11.x, v11.y);
        }
    }
    __syncthreads();   // Ws ready

    float o[8][4];
    #pragma unroll
    for (int nt = 0; nt < 8; nt++) { o[nt][0]=o[nt][1]=o[nt][2]=o[nt][3]=0.f; }

    #pragma unroll
    for (int nt = 0; nt < 8; nt++) {
        #pragma unroll
        for (int kc0 = 0; kc0 < 4; kc0 += 2) {
            uint32_t b0, b1, b2, b3;
            ldsm_x4(b0, b1, b2, b3,
                &Ws[(nt * 8 + lr) * PITCH + kc0 * 16 + lc * 8]);
            mma16816(o[nt], a[kc0][0], a[kc0][1], a[kc0][2], a[kc0][3], b0, b1);
            mma16816(o[nt], a[kc0+1][0], a[kc0+1][1], a[kc0+1][2], a[kc0+1][3], b2, b3);
        }
    }

    #pragma unroll
    for (int nt = 0; nt < 8; nt++) {
        int e = nt * 8 + 2 * t4;
        int grow = row0 + mw + g;
        int n = grow >> 15, rem = grow & 32767;
        int l = rem >> 4, h = rem & 15;
        *(__half2*)(out + ((size_t)(n * NH + h) * L_S + l) * HD + e)
            = __floats2half2_rn(o[nt][0] * oscale, o[nt][1] * oscale);
        grow += 8; n = grow >> 15; rem = grow & 32767; l = rem >> 4; h = rem & 15;
        *(__half2*)(out + ((size_t)(n * NH + h) * L_S + l) * HD + e)
            = __floats2half2_rn(o[nt][2] * oscale, o[nt][3] * oscale);
    }
}

// ---------------------------------------------------------------------------
// Kernel 2: flash attention, pipelined (128,4), f16x2 exp softmax.
// Row sums via HADD2 tree over P fragments (FMA pipe) instead of the
// ones-column MMA (saves ~11% of GEMM2 tensor work).
// ---------------------------------------------------------------------------
__global__ __launch_bounds__(128, 4) void attn13()
{
    extern __shared__ __half sm8[];
    __half* Ks = sm8;                       // 3 slots of 64*PITCH
    __half* Vs = sm8 + 3 * 64 * PITCH;      // 3 slots of 64*PITCH

    const int nh = blockIdx.x;
    const int qt = blockIdx.y;
    const int n  = nh >> 4, h = nh & 15;
    const int q0 = qt * 64;

    const __half* Qg = g_qp + (size_t)nh * L_S * HD;
    const __half* Kg = g_kp + (size_t)nh * L_S * HD;
    const __half* Vg = g_vp + (size_t)nh * L_S * HD;

    const int tid = threadIdx.x;
    const int warp = tid >> 5, lane = tid & 31;
    const int g = lane >> 2, t4 = lane & 3;
    const int mw = warp * 16;
    const int lr = lane & 7, lc = lane >> 3;

    uint32_t qa[4][4];
    {
        const __half* Qr0 = Qg + (size_t)(q0 + mw + g    ) * HD;
        const __half* Qr1 = Qg + (size_t)(q0 + mw + g + 8) * HD;
        #pragma unroll
        for (int kc = 0; kc < 4; kc++) {
            qa[kc][0] = *(const uint32_t*)&Qr0[kc * 16 + 2 * t4];
            qa[kc][1] = *(const uint32_t*)&Qr1[kc * 16 + 2 * t4];
            qa[kc][2] = *(const uint32_t*)&Qr0[kc * 16 + 2 * t4 + 8];
            qa[kc][3] = *(const uint32_t*)&Qr1[kc * 16 + 2 * t4 + 8];
        }
    }

    const unsigned char* flags = g_mflag + ((size_t)n * 32 + qt) * 32;
    const uint32_t* Mp = g_mpack + (size_t)n * L_S * 64;

    auto load_k = [&](int t) {
        __half* dst = Ks + (t % 3) * 64 * PITCH;
        const __half* src = Kg + (size_t)t * 64 * HD;
        #pragma unroll
        for (int it = 0; it < 4; it++) {
            int c = tid + it * 128;
            int r = c >> 3, off = (c & 7) * 8;
            cp16(&dst[r * PITCH + off], &src[(size_t)r * HD + off]);
        }
    };
    auto load_v = [&](int t) {
        __half* dst = Vs + (t % 3) * 64 * PITCH;
        const __half* src = Vg + (size_t)t * 64 * HD;
        #pragma unroll
        for (int it = 0; it < 4; it++) {
            int c = tid + it * 128;
            int r = c >> 3, off = (c & 7) * 8;
            cp16(&dst[r * PITCH + off], &src[(size_t)r * HD + off]);
        }
    };

    float l0 = 0.f, l1 = 0.f;

    auto gemm1 = [&](const __half* Kt, int t, uint32_t (&pout)[4][4]) {
        const bool do_mask = !flags[t];
        uint64_t w0 = 0, w1 = 0;
        if (do_mask) {
            w0 = *(const uint64_t*)&Mp[(size_t)(q0 + mw + g    ) * 64 + t * 2];
            w1 = *(const uint64_t*)&Mp[(size_t)(q0 + mw + g + 8) * 64 + t * 2];
        }
        #pragma unroll
        for (int ntp = 0; ntp < 4; ntp++) {
            const int nt0 = 2 * ntp, nt1 = 2 * ntp + 1;
            float s0[4] = {0.f, 0.f, 0.f, 0.f};
            float s1[4] = {0.f, 0.f, 0.f, 0.f};
            #pragma unroll
            for (int kc0 = 0; kc0 < 4; kc0 += 2) {
                uint32_t b0, b1, b2, b3;
                ldsm_x4(b0, b1, b2, b3,
                    &Kt[(nt0 * 8 + lr) * PITCH + kc0 * 16 + lc * 8]);
                mma16816(s0, qa[kc0][0], qa[kc0][1], qa[kc0][2], qa[kc0][3], b0, b1);
                mma16816(s0, qa[kc0+1][0], qa[kc0+1][1], qa[kc0+1][2], qa[kc0+1][3], b2, b3);
                ldsm_x4(b0, b1, b2, b3,
                    &Kt[(nt1 * 8 + lr) * PITCH + kc0 * 16 + lc * 8]);
                mma16816(s1, qa[kc0][0], qa[kc0][1], qa[kc0][2], qa[kc0][3], b0, b1);
                mma16816(s1, qa[kc0+1][0], qa[kc0+1][1], qa[kc0+1][2], qa[kc0+1][3], b2, b3);
            }
            if (do_mask) {
                int bit0 = nt0 * 8 + 2 * t4;
                int bit1 = nt1 * 8 + 2 * t4;
                if (!((w0 >> bit0) & 1))       s0[0] = -1e30f;
                if (!((w0 >> (bit0 + 1)) & 1)) s0[1] = -1e30f;
                if (!((w1 >> bit0) & 1))       s0[2] = -1e30f;
                if (!((w1 >> (bit0 + 1)) & 1)) s0[3] = -1e30f;
                if (!((w0 >> bit1) & 1))       s1[0] = -1e30f;
                if (!((w0 >> (bit1 + 1)) & 1)) s1[1] = -1e30f;
                if (!((w1 >> bit1) & 1))       s1[2] = -1e30f;
                if (!((w1 >> (bit1 + 1)) & 1)) s1[3] = -1e30f;
            }
            pout[ntp][0] = h2exp2(packh2(s0[0], s0[1]));
            pout[ntp][1] = h2exp2(packh2(s0[2], s0[3]));
            pout[ntp][2] = h2exp2(packh2(s1[0], s1[1]));
            pout[ntp][3] = h2exp2(packh2(s1[2], s1[3]));
        }
        // row sums on the FMA pipe (HADD2 tree, then f32 accumulate)
        __half2 h0 = __hadd2(__hadd2(u2h2(pout[0][0]), u2h2(pout[0][2])),
                             __hadd2(u2h2(pout[1][0]), u2h2(pout[1][2])));
        __half2 h0b = __hadd2(__hadd2(u2h2(pout[2][0]), u2h2(pout[2][2])),
                              __hadd2(u2h2(pout[3][0]), u2h2(pout[3][2])));
        h0 = __hadd2(h0, h0b);
        __half2 h1 = __hadd2(__hadd2(u2h2(pout[0][1]), u2h2(pout[0][3])),
                             __hadd2(u2h2(pout[1][1]), u2h2(pout[1][3])));
        __half2 h1b = __hadd2(__hadd2(u2h2(pout[2][1]), u2h2(pout[2][3])),
                              __hadd2(u2h2(pout[3][1]), u2h2(pout[3][3])));
        h1 = __hadd2(h1, h1b);
        float2 f0 = __half22float2(h0);
        float2 f1 = __half22float2(h1);
        l0 += f0.x + f0.y;
        l1 += f1.x + f1.y;
    };

    float o[8][4];
    #pragma unroll
    for (int ne = 0; ne < 8; ne++) { o[ne][0]=o[ne][1]=o[ne][2]=o[ne][3]=0.f; }

    auto gemm2 = [&](int kt, const uint32_t (&p)[4][4]) {
        const __half* Vt = Vs + (kt % 3) * 64 * PITCH;
        #pragma unroll
        for (int ne = 0; ne < 8; ne++) {
            #pragma unroll
            for (int kc0 = 0; kc0 < 4; kc0 += 2) {
                uint32_t b0, b1, b2, b3;
                ldsm_x4_t(b0, b1, b2, b3,
                    &Vt[(kc0 * 16 + lane) * PITCH + ne * 8]);
                mma16816(o[ne], p[kc0][0], p[kc0][1], p[kc0][2], p[kc0][3], b0, b1);
                mma16816(o[ne], p[kc0+1][0], p[kc0+1][1], p[kc0+1][2], p[kc0+1][3], b2, b3);
            }
        }
    };

    load_k(0); load_v(0); load_k(1); load_v(1); load_k(2);
    cp_commit();
    cp_wait<0>();
    __syncthreads();

    uint32_t pa[4][4], pn[4][4];
    gemm1(Ks, 0, pa);

    const int NT = L_S / 64;               // 32, even
    #pragma unroll 1
    for (int kt = 0; kt < NT; kt += 2) {
        cp_wait<2>();
        __syncthreads();
        gemm1(Ks + ((kt + 1) % 3) * 64 * PITCH, kt + 1, pn);
        gemm2(kt, pa);
        if (kt + 2 < NT) load_v(kt + 2);
        cp_commit();
        if (kt + 3 < NT) load_k(kt + 3);
        cp_commit();

        cp_wait<2>();
        __syncthreads();
        if (kt + 2 < NT)
            gemm1(Ks + ((kt + 2) % 3) * 64 * PITCH, kt + 2, pa);
        gemm2(kt + 1, pn);
        if (kt + 3 < NT) load_v(kt + 3);
        cp_commit();
        if (kt + 4 < NT) load_k(kt + 4);
        cp_commit();
    }

    // cross-quad reduction (t4 lanes)
    l0 += __shfl_xor_sync(0xffffffffu, l0, 1);
    l0 += __shfl_xor_sync(0xffffffffu, l0, 2);
    l1 += __shfl_xor_sync(0xffffffffu, l1, 1);
    l1 += __shfl_xor_sync(0xffffffffu, l1, 2);

    float inv0 = 1.f / l0, inv1 = 1.f / l1;
    int row = q0 + mw + g;
    __half* base0 = g_att + ((size_t)n * L_S + row) * EMB + h * HD;
    __half* base1 = base0 + (size_t)8 * EMB;
    #pragma unroll
    for (int ne = 0; ne < 8; ne++) {
        int e = ne * 8 + 2 * t4;
        *(__half2*)(base0 + e) = __floats2half2_rn(o[ne][0] * inv0, o[ne][1] * inv0);
        *(__half2*)(base1 + e) = __floats2half2_rn(o[ne][2] * inv1, o[ne][3] * inv1);
    }
}

// ---------------------------------------------------------------------------
// Kernel 3: out projection, BM=128 x BN=128 per block, cp.async 2-stage.
// ---------------------------------------------------------------------------
__global__ __launch_bounds__(256) void out_mma3(
    const float* __restrict__ bo, float* __restrict__ out)
{
    extern __shared__ __half sm[];
    __half* As[2] = { sm, sm + 128 * PITCH };
    __half* Bs[2] = { sm + 2 * 128 * PITCH, sm + 3 * 128 * PITCH };

    const int m0 = blockIdx.x * 128;
    const int e0 = blockIdx.y * 128;
    const int tid = threadIdx.x;
    const int warp = tid >> 5, lane = tid & 31;
    const int g = lane >> 2, t4 = lane & 3;
    const int mw = warp * 16;
    const int lr = lane & 7, lc = lane >> 3;

    auto load_ab = [&](int f, int b) {
        const int f0 = f * 64;
        #pragma unroll
        for (int it = 0; it < 4; it++) {
            int c = tid + it * 256;
            int r = c >> 3, off = (c & 7) * 8;
            cp16(&As[b][r * PITCH + off], &g_att[(size_t)(m0 + r) * EMB + f0 + off]);
        }
        #pragma unroll
        for (int it = 0; it < 4; it++) {
            int c = tid + it * 256;
            int r = c >> 3, off = (c & 7) * 8;
            cp16(&Bs[b][r * PITCH + off], &g_woh[(size_t)(e0 + r) * EMB + f0 + off]);
        }
        cp_commit();
    };

    float o[16][4];
    #pragma unroll
    for (int nt = 0; nt < 16; nt++) { o[nt][0]=o[nt][1]=o[nt][2]=o[nt][3]=0.f; }

    load_ab(0, 0);
    load_ab(1, 1);

    const int NF = EMB / 64;
    for (int f = 0; f < NF; f++) {
        const int b = f & 1;
        if (f == NF - 1) cp_wait<0>(); else cp_wait<1>();
        __syncthreads();

        uint32_t a[4][4];
        #pragma unroll
        for (int kc = 0; kc < 4; kc++) {
            ldsm_x4(a[kc][0], a[kc][1], a[kc][2], a[kc][3],
                &As[b][(mw + lr + ((lane >> 3) & 1) * 8) * PITCH
                       + kc * 16 + (lane >> 4) * 8]);
        }
        #pragma unroll
        for (int nt = 0; nt < 16; nt++) {
            #pragma unroll
            for (int kc0 = 0; kc0 < 4; kc0 += 2) {
                uint32_t b0, b1, b2, b3;
                ldsm_x4(b0, b1, b2, b3,
                    &Bs[b][(nt * 8 + lr) * PITCH + kc0 * 16 + lc * 8]);
                mma16816(o[nt], a[kc0][0], a[kc0][1], a[kc0][2], a[kc0][3], b0, b1);
                mma16816(o[nt], a[kc0+1][0], a[kc0+1][1], a[kc0+1][2], a[kc0+1][3], b2, b3);
            }
        }

        __syncthreads();
        if (f + 2 < NF) load_ab(f + 2, b);
    }

    #pragma unroll
    for (int nt = 0; nt < 16; nt++) {
        int e = e0 + nt * 8 + 2 * t4;
        float b0v = bo[e], b1v = bo[e + 1];
        float2* d0 = (float2*)(out + (size_t)(m0 + mw + g    ) * EMB + e);
        float2* d1 = (float2*)(out + (size_t)(m0 + mw + g + 8) * EMB + e);
        *d0 = make_float2(o[nt][0] + b0v, o[nt][1] + b1v);
        *d1 = make_float2(o[nt][2] + b0v, o[nt][3] + b1v);
    }
}

// ---------------------------------------------------------------------------
extern "C" void kernel_launch(void* const* d_in, const int* in_sizes, int n_in,
                              void* d_out, int out_size)
{
    const float* values  = (const float*)d_in[0];
    const float* keys    = (const float*)d_in[1];
    const float* queries = (const float*)d_in[2];
    const int*   mask    = (const int*)  d_in[3];
    const float* Wv      = (const float*)d_in[4];
    const float* Wk      = (const float*)d_in[5];
    const float* Wq      = (const float*)d_in[6];
    const float* Wo      = (const float*)d_in[7];
    const float* bo      = (const float*)d_in[8];
    float* out = (float*)d_out;

    prep<<<3072, 256>>>(queries, keys, values, Wq, Wk, Wv, Wo, mask);

    const int smem_attn = 6 * 64 * PITCH * sizeof(__half);   // 55296 B
    cudaFuncSetAttribute(attn13, cudaFuncAttributeMaxDynamicSharedMemorySize, smem_attn);
    attn13<<<dim3(N_B * NH, L_S / 64), 128, smem_attn>>>();

    const int smem_out = 4 * 128 * PITCH * sizeof(__half);   // 73728 B
    cudaFuncSetAttribute(out_mma3, cudaFuncAttributeMaxDynamicSharedMemorySize, smem_out);
    out_mma3<<<dim3((N_B * L_S) / 128, EMB / 128), 256, smem_out>>>(bo, out);
}